// round 1
// baseline (speedup 1.0000x reference)
#include <cuda_runtime.h>

// Problem sizes (fixed by the reference)
static constexpr int NL = 2048;   // labeled rows
static constexpr int NU = 6144;   // unlabeled rows
static constexpr int NT = 8192;   // NL + NU
static constexpr int D  = 512;    // feature dim
static constexpr int CC = 1000;   // classes

// Scratch (device globals: allocation-free per harness rules)
__device__ float g_n[NT * D];                 // L2-normalized feats   (16.8 MB)
__device__ float g_cv[NT * CC];               // class_val             (32.8 MB)
__device__ float g_S[(size_t)NT * NT];        // attention matrix      (268 MB)

// ---------------------------------------------------------------------------
// Fast exp: FMA-only (avoids MUFU throughput wall: 67M exps on MUFU ~0.45ms).
// Range-reduced degree-6 Taylor, |rel err| < 1.5e-7 for x in [-80, 0].
// ---------------------------------------------------------------------------
__device__ __forceinline__ float fast_expf(float x) {
    float z = x * 1.4426950408889634f;           // x * log2(e)
    float n = rintf(z);
    float r = fmaf(n, -0.6931471824645996f, x);  // x - n*ln2_hi
    r = fmaf(n, 1.9046542743e-9f, r);            // - n*ln2_lo  (lo is negative)
    float p = 1.3888889225e-3f;                  // 1/720
    p = fmaf(p, r, 8.3333337680e-3f);            // 1/120
    p = fmaf(p, r, 4.1666667908e-2f);            // 1/24
    p = fmaf(p, r, 1.6666667163e-1f);            // 1/6
    p = fmaf(p, r, 5.0e-1f);
    p = fmaf(p, r, 1.0f);
    p = fmaf(p, r, 1.0f);
    int e = (int)n;                              // n <= 0 here; e+127 >= ~98
    float s = __int_as_float((e + 127) << 23);   // 2^n
    return p * s;
}

// ---------------------------------------------------------------------------
// Packed fp32x2 FMA (Blackwell FFMA2 — 2x fp32 throughput vs 3-reg FFMA)
// ---------------------------------------------------------------------------
__device__ __forceinline__ void fma2(unsigned long long& d,
                                     unsigned long long a,
                                     unsigned long long b) {
    asm("fma.rn.f32x2 %0, %1, %2, %3;" : "=l"(d) : "l"(a), "l"(b), "l"(d));
}

__device__ __forceinline__ float2 f2unpack(unsigned long long v) {
    float2 r;
    asm("mov.b64 {%0, %1}, %2;" : "=f"(r.x), "=f"(r.y) : "l"(v));
    return r;
}

// ---------------------------------------------------------------------------
// Block reductions (256 threads)
// ---------------------------------------------------------------------------
__device__ __forceinline__ float blockMax256(float v) {
    __shared__ float s[8];
    #pragma unroll
    for (int o = 16; o > 0; o >>= 1) v = fmaxf(v, __shfl_xor_sync(0xffffffffu, v, o));
    if ((threadIdx.x & 31) == 0) s[threadIdx.x >> 5] = v;
    __syncthreads();
    float r = s[0];
    #pragma unroll
    for (int i = 1; i < 8; i++) r = fmaxf(r, s[i]);
    __syncthreads();
    return r;
}

__device__ __forceinline__ float blockSum256(float v) {
    __shared__ float s[8];
    #pragma unroll
    for (int o = 16; o > 0; o >>= 1) v += __shfl_xor_sync(0xffffffffu, v, o);
    if ((threadIdx.x & 31) == 0) s[threadIdx.x >> 5] = v;
    __syncthreads();
    float r = s[0];
    #pragma unroll
    for (int i = 1; i < 8; i++) r += s[i];
    __syncthreads();
    return r;
}

// ---------------------------------------------------------------------------
// Kernel 1: L2-normalize concat(lb_feat, anchor_feat) -> g_n   (8192 x 512)
// One block per row, 128 threads, one float4 per thread.
// ---------------------------------------------------------------------------
__global__ void normalize_kernel(const float* __restrict__ lb_feat,
                                 const float* __restrict__ anchor) {
    const int row = blockIdx.x;
    const int t = threadIdx.x;
    const float* src = (row < NL) ? lb_feat + (size_t)row * D
                                  : anchor + (size_t)(row - NL) * D;
    float4 v = ((const float4*)src)[t];
    float ss = v.x * v.x + v.y * v.y + v.z * v.z + v.w * v.w;
    #pragma unroll
    for (int o = 16; o > 0; o >>= 1) ss += __shfl_xor_sync(0xffffffffu, ss, o);
    __shared__ float ws[4];
    if ((t & 31) == 0) ws[t >> 5] = ss;
    __syncthreads();
    float tot = ws[0] + ws[1] + ws[2] + ws[3];
    float sc = 1.0f / fmaxf(sqrtf(tot), 1e-12f);
    float4 o4 = make_float4(v.x * sc, v.y * sc, v.z * sc, v.w * sc);
    ((float4*)(g_n + (size_t)row * D))[t] = o4;
}

// ---------------------------------------------------------------------------
// Kernel 2: class_val = concat(lb_one_hot, softmax(logits_x_ulb_1)) -> g_cv
// One block per row, 256 threads.
// ---------------------------------------------------------------------------
__global__ void classval_kernel(const float* __restrict__ lb_one_hot,
                                const float* __restrict__ logits) {
    const int row = blockIdx.x;
    const int t = threadIdx.x;
    float* dst = g_cv + (size_t)row * CC;
    if (row < NL) {
        const float* src = lb_one_hot + (size_t)row * CC;
        for (int j = t; j < CC; j += 256) dst[j] = src[j];
        return;
    }
    const float* src = logits + (size_t)(row - NL) * CC;
    float v[4];
    float mx = -1e30f;
    #pragma unroll
    for (int q = 0; q < 4; q++) {
        int j = t + q * 256;
        v[q] = (j < CC) ? src[j] : -1e30f;
        mx = fmaxf(mx, v[q]);
    }
    mx = blockMax256(mx);
    float sum = 0.f;
    #pragma unroll
    for (int q = 0; q < 4; q++) {
        int j = t + q * 256;
        float e = (j < CC) ? fast_expf(v[q] - mx) : 0.f;
        v[q] = e;
        sum += e;
    }
    sum = blockSum256(sum);
    float inv = 1.0f / sum;
    #pragma unroll
    for (int q = 0; q < 4; q++) {
        int j = t + q * 256;
        if (j < CC) dst[j] = v[q] * inv;
    }
}

// ---------------------------------------------------------------------------
// Kernel 3: GEMM1  S = 10 * (n @ n^T)      [8192 x 8192], K = 512
// 128x128x16 tiles, 256 threads, 8x8 microtile in packed f32x2 accumulators.
// A operand stored DUPLICATED in smem so LDS.64 yields the (a,a) pair FFMA2
// needs; B stored k-major so LDS.64 gives natural (b[j], b[j+1]) pairs.
// ---------------------------------------------------------------------------
__global__ __launch_bounds__(256, 2) void gemm1_kernel() {
    __shared__ float Ad[16][256];
    __shared__ float Bs[16][128];
    const int t  = threadIdx.x;
    const int tx = t & 15, ty = t >> 4;
    const int i0 = blockIdx.y * 128, j0 = blockIdx.x * 128;
    const int lr = t >> 2;         // 0..63
    const int lk = (t & 3) * 4;    // 0,4,8,12

    const float* ap0 = g_n + (size_t)(i0 + lr) * D + lk;
    const float* ap1 = g_n + (size_t)(i0 + lr + 64) * D + lk;
    const float* bp0 = g_n + (size_t)(j0 + lr) * D + lk;
    const float* bp1 = g_n + (size_t)(j0 + lr + 64) * D + lk;

    unsigned long long acc[8][4];
    #pragma unroll
    for (int i = 0; i < 8; i++)
        #pragma unroll
        for (int j = 0; j < 4; j++) acc[i][j] = 0ULL;

    for (int k0 = 0; k0 < D; k0 += 16) {
        float4 a0 = *(const float4*)(ap0 + k0);
        float4 a1 = *(const float4*)(ap1 + k0);
        float4 b0 = *(const float4*)(bp0 + k0);
        float4 b1 = *(const float4*)(bp1 + k0);
        __syncthreads();
        int r2 = 2 * lr;
        Ad[lk + 0][r2] = a0.x; Ad[lk + 0][r2 + 1] = a0.x;
        Ad[lk + 1][r2] = a0.y; Ad[lk + 1][r2 + 1] = a0.y;
        Ad[lk + 2][r2] = a0.z; Ad[lk + 2][r2 + 1] = a0.z;
        Ad[lk + 3][r2] = a0.w; Ad[lk + 3][r2 + 1] = a0.w;
        int r2b = r2 + 128;
        Ad[lk + 0][r2b] = a1.x; Ad[lk + 0][r2b + 1] = a1.x;
        Ad[lk + 1][r2b] = a1.y; Ad[lk + 1][r2b + 1] = a1.y;
        Ad[lk + 2][r2b] = a1.z; Ad[lk + 2][r2b + 1] = a1.z;
        Ad[lk + 3][r2b] = a1.w; Ad[lk + 3][r2b + 1] = a1.w;
        Bs[lk + 0][lr] = b0.x; Bs[lk + 1][lr] = b0.y;
        Bs[lk + 2][lr] = b0.z; Bs[lk + 3][lr] = b0.w;
        Bs[lk + 0][lr + 64] = b1.x; Bs[lk + 1][lr + 64] = b1.y;
        Bs[lk + 2][lr + 64] = b1.z; Bs[lk + 3][lr + 64] = b1.w;
        __syncthreads();
        #pragma unroll
        for (int kk = 0; kk < 16; kk++) {
            unsigned long long a2[8], b2[4];
            #pragma unroll
            for (int i = 0; i < 8; i++)
                a2[i] = *(const unsigned long long*)&Ad[kk][2 * (ty * 8 + i)];
            #pragma unroll
            for (int j = 0; j < 4; j++)
                b2[j] = *(const unsigned long long*)&Bs[kk][tx * 8 + 2 * j];
            #pragma unroll
            for (int i = 0; i < 8; i++)
                #pragma unroll
                for (int j = 0; j < 4; j++)
                    fma2(acc[i][j], a2[i], b2[j]);
        }
    }

    #pragma unroll
    for (int i = 0; i < 8; i++) {
        float* crow = g_S + (size_t)(i0 + ty * 8 + i) * NT + j0 + tx * 8;
        float2 p0 = f2unpack(acc[i][0]);
        float2 p1 = f2unpack(acc[i][1]);
        float2 p2 = f2unpack(acc[i][2]);
        float2 p3 = f2unpack(acc[i][3]);
        *(float4*)(crow)     = make_float4(p0.x * 10.f, p0.y * 10.f, p1.x * 10.f, p1.y * 10.f);
        *(float4*)(crow + 4) = make_float4(p2.x * 10.f, p2.y * 10.f, p3.x * 10.f, p3.y * 10.f);
    }
}

// ---------------------------------------------------------------------------
// Kernel 4: row softmax of S in place. One block per row (8192 floats),
// 256 threads x 8 float4 in registers -> single global read + single write.
// ---------------------------------------------------------------------------
__global__ void softmaxS_kernel() {
    const int t = threadIdx.x;
    float4* row = (float4*)(g_S + (size_t)blockIdx.x * NT);
    float4 v[8];
    float mx = -1e30f;
    #pragma unroll
    for (int q = 0; q < 8; q++) {
        v[q] = row[t + q * 256];
        mx = fmaxf(mx, fmaxf(fmaxf(v[q].x, v[q].y), fmaxf(v[q].z, v[q].w)));
    }
    mx = blockMax256(mx);
    float sum = 0.f;
    #pragma unroll
    for (int q = 0; q < 8; q++) {
        v[q].x = fast_expf(v[q].x - mx);
        v[q].y = fast_expf(v[q].y - mx);
        v[q].z = fast_expf(v[q].z - mx);
        v[q].w = fast_expf(v[q].w - mx);
        sum += (v[q].x + v[q].y) + (v[q].z + v[q].w);
    }
    sum = blockSum256(sum);
    float inv = 1.0f / sum;
    #pragma unroll
    for (int q = 0; q < 8; q++) {
        v[q].x *= inv; v[q].y *= inv; v[q].z *= inv; v[q].w *= inv;
        row[t + q * 256] = v[q];
    }
}

// ---------------------------------------------------------------------------
// Kernel 5: GEMM2  out = P @ class_val    [8192 x 1000], K = 8192
// Same tiling; B columns guarded against CC=1000 (CC%4==0 so float4 guards
// are exact). Writes directly into d_out (new_lb || new_ulb1 is contiguous).
// ---------------------------------------------------------------------------
__global__ __launch_bounds__(256, 2) void gemm2_kernel(float* __restrict__ out) {
    __shared__ float Ad[16][256];
    __shared__ float Bs[16][128];
    const int t  = threadIdx.x;
    const int tx = t & 15, ty = t >> 4;
    const int i0 = blockIdx.y * 128, j0 = blockIdx.x * 128;
    const int lr = t >> 2;         // 0..63
    const int lk = (t & 3) * 4;    // 0,4,8,12
    const int bk = t >> 5;         // 0..7
    const int bc = (t & 31) * 4;   // 0..124
    const int bcol = j0 + bc;
    const bool bok = (bcol < CC);

    const float* abase0 = g_S + (size_t)(i0 + lr) * NT + lk;
    const float* abase1 = abase0 + (size_t)64 * NT;

    unsigned long long acc[8][4];
    #pragma unroll
    for (int i = 0; i < 8; i++)
        #pragma unroll
        for (int j = 0; j < 4; j++) acc[i][j] = 0ULL;

    for (int k0 = 0; k0 < NT; k0 += 16) {
        float4 a0 = *(const float4*)(abase0 + k0);
        float4 a1 = *(const float4*)(abase1 + k0);
        float4 b0 = make_float4(0.f, 0.f, 0.f, 0.f);
        float4 b1 = b0;
        if (bok) {
            b0 = *(const float4*)(g_cv + (size_t)(k0 + bk) * CC + bcol);
            b1 = *(const float4*)(g_cv + (size_t)(k0 + bk + 8) * CC + bcol);
        }
        __syncthreads();
        int r2 = 2 * lr;
        Ad[lk + 0][r2] = a0.x; Ad[lk + 0][r2 + 1] = a0.x;
        Ad[lk + 1][r2] = a0.y; Ad[lk + 1][r2 + 1] = a0.y;
        Ad[lk + 2][r2] = a0.z; Ad[lk + 2][r2 + 1] = a0.z;
        Ad[lk + 3][r2] = a0.w; Ad[lk + 3][r2 + 1] = a0.w;
        int r2b = r2 + 128;
        Ad[lk + 0][r2b] = a1.x; Ad[lk + 0][r2b + 1] = a1.x;
        Ad[lk + 1][r2b] = a1.y; Ad[lk + 1][r2b + 1] = a1.y;
        Ad[lk + 2][r2b] = a1.z; Ad[lk + 2][r2b + 1] = a1.z;
        Ad[lk + 3][r2b] = a1.w; Ad[lk + 3][r2b + 1] = a1.w;
        *(float4*)&Bs[bk][bc]     = b0;
        *(float4*)&Bs[bk + 8][bc] = b1;
        __syncthreads();
        #pragma unroll
        for (int kk = 0; kk < 16; kk++) {
            unsigned long long a2[8], b2[4];
            #pragma unroll
            for (int i = 0; i < 8; i++)
                a2[i] = *(const unsigned long long*)&Ad[kk][2 * (ty * 8 + i)];
            #pragma unroll
            for (int j = 0; j < 4; j++)
                b2[j] = *(const unsigned long long*)&Bs[kk][tx * 8 + 2 * j];
            #pragma unroll
            for (int i = 0; i < 8; i++)
                #pragma unroll
                for (int j = 0; j < 4; j++)
                    fma2(acc[i][j], a2[i], b2[j]);
        }
    }

    const int ccol = j0 + tx * 8;
    #pragma unroll
    for (int i = 0; i < 8; i++) {
        float* crow = out + (size_t)(i0 + ty * 8 + i) * CC + ccol;
        float2 p0 = f2unpack(acc[i][0]);
        float2 p1 = f2unpack(acc[i][1]);
        float2 p2 = f2unpack(acc[i][2]);
        float2 p3 = f2unpack(acc[i][3]);
        if (ccol < CC)
            *(float4*)(crow) = make_float4(p0.x, p0.y, p1.x, p1.y);
        if (ccol + 4 < CC)
            *(float4*)(crow + 4) = make_float4(p2.x, p2.y, p3.x, p3.y);
    }
}

// ---------------------------------------------------------------------------
// Launch. Output layout (float32, tuple order):
//   [0)          anchor_feat      6144*512  = 3145728
//   [3145728)    positive_feat    6144*512
//   [6291456)    lb_feat          2048*512  = 1048576
//   [7340032)    lb_one_hot       2048*1000 = 2048000
//   [9388032)    new_lb           2048*1000   \  contiguous 8192x1000:
//   [11436032)   new_ulb1         6144*1000   /  GEMM2 writes both at once
//   [17580032)   logits_x_ulb_2   6144*1000
// ---------------------------------------------------------------------------
extern "C" void kernel_launch(void* const* d_in, const int* in_sizes, int n_in,
                              void* d_out, int out_size) {
    const float* anchor   = (const float*)d_in[0];
    const float* positive = (const float*)d_in[1];
    const float* lb_feat  = (const float*)d_in[2];
    const float* lb_oh    = (const float*)d_in[3];
    const float* lg_ulb1  = (const float*)d_in[5];
    const float* lg_ulb2  = (const float*)d_in[6];
    float* out = (float*)d_out;

    // Pass-through outputs (device-to-device async copies: graph-capturable)
    cudaMemcpyAsync(out,             anchor,   (size_t)NU * D  * sizeof(float), cudaMemcpyDeviceToDevice, 0);
    cudaMemcpyAsync(out + 3145728,   positive, (size_t)NU * D  * sizeof(float), cudaMemcpyDeviceToDevice, 0);
    cudaMemcpyAsync(out + 6291456,   lb_feat,  (size_t)NL * D  * sizeof(float), cudaMemcpyDeviceToDevice, 0);
    cudaMemcpyAsync(out + 7340032,   lb_oh,    (size_t)NL * CC * sizeof(float), cudaMemcpyDeviceToDevice, 0);
    cudaMemcpyAsync(out + 17580032,  lg_ulb2,  (size_t)NU * CC * sizeof(float), cudaMemcpyDeviceToDevice, 0);

    normalize_kernel<<<NT, 128>>>(lb_feat, anchor);
    classval_kernel<<<NT, 256>>>(lb_oh, lg_ulb1);
    gemm1_kernel<<<dim3(64, 64), 256>>>();
    softmaxS_kernel<<<NT, 256>>>();
    gemm2_kernel<<<dim3(8, 64), 256>>>(out + 9388032);
}

// round 3
// speedup vs baseline: 6.3915x; 6.3915x over previous
#include <cuda_runtime.h>
#include <cuda_fp16.h>
#include <cstdint>

// Problem sizes
static constexpr int NL = 2048;
static constexpr int NU = 6144;
static constexpr int NT = 8192;   // NL + NU
static constexpr int D  = 512;
static constexpr int CC = 1000;
static constexpr int CCP = 1024;  // padded classes

// Scratch (device globals; no allocation allowed)
__device__ __half g_nh[(size_t)NT * D];      // normalized feats hi fp16 (8MB)
__device__ __half g_nl[(size_t)NT * D];      // normalized feats lo fp16 (8MB)
__device__ float  g_cv[(size_t)NT * CC];     // class_val fp32 (32.8MB)
__device__ __half g_cvT[(size_t)CCP * NT];   // class_val^T fp16 (16.8MB)
__device__ __half g_E[(size_t)NT * NT];      // exp(S) fp16 (134MB)
__device__ float  g_rsum[NT];                // softmax denominators

// ============================================================================
// Helpers
// ============================================================================
__device__ __forceinline__ uint32_t smem_u32(const void* p) {
    uint32_t a;
    asm("{ .reg .u64 t; cvta.to.shared.u64 t, %1; cvt.u32.u64 %0, t; }" : "=r"(a) : "l"(p));
    return a;
}
// swizzled byte offset inside a tile of 128B rows (8 x 16B segments per row)
__device__ __forceinline__ uint32_t smoff(int row, int seg) {
    return (uint32_t)(row * 128 + ((seg ^ (row & 7)) << 4));
}
#define CP16(dst, src) \
    asm volatile("cp.async.cg.shared.global [%0], [%1], 16;" :: "r"(dst), "l"(src) : "memory")
#define CP_COMMIT() asm volatile("cp.async.commit_group;" ::: "memory")
#define CP_WAIT1() asm volatile("cp.async.wait_group 1;" ::: "memory")
#define CP_WAIT0() asm volatile("cp.async.wait_group 0;" ::: "memory")

__device__ __forceinline__ void ldm_x4(uint32_t* r, uint32_t addr) {
    asm volatile("ldmatrix.sync.aligned.m8n8.x4.shared.b16 {%0,%1,%2,%3}, [%4];"
                 : "=r"(r[0]), "=r"(r[1]), "=r"(r[2]), "=r"(r[3]) : "r"(addr));
}
__device__ __forceinline__ void mma16816(float* d, const uint32_t* a, const uint32_t* b) {
    asm volatile(
        "mma.sync.aligned.m16n8k16.row.col.f32.f16.f16.f32 "
        "{%0,%1,%2,%3}, {%4,%5,%6,%7}, {%8,%9}, {%0,%1,%2,%3};"
        : "+f"(d[0]), "+f"(d[1]), "+f"(d[2]), "+f"(d[3])
        : "r"(a[0]), "r"(a[1]), "r"(a[2]), "r"(a[3]), "r"(b[0]), "r"(b[1]));
}

// FMA-only exp, valid for |x| <= ~11, rel err < 2e-7
__device__ __forceinline__ float fast_expf(float x) {
    float z = x * 1.4426950408889634f;
    float n = rintf(z);
    float r = fmaf(n, -0.6931471824645996f, x);
    r = fmaf(n, 1.9046542743e-9f, r);
    float p = 1.3888889225e-3f;
    p = fmaf(p, r, 8.3333337680e-3f);
    p = fmaf(p, r, 4.1666667908e-2f);
    p = fmaf(p, r, 1.6666667163e-1f);
    p = fmaf(p, r, 5.0e-1f);
    p = fmaf(p, r, 1.0f);
    p = fmaf(p, r, 1.0f);
    float s = __int_as_float(((int)n + 127) << 23);
    return p * s;
}

__device__ __forceinline__ float blockMax256(float v) {
    __shared__ float s[8];
    #pragma unroll
    for (int o = 16; o > 0; o >>= 1) v = fmaxf(v, __shfl_xor_sync(0xffffffffu, v, o));
    if ((threadIdx.x & 31) == 0) s[threadIdx.x >> 5] = v;
    __syncthreads();
    float r = s[0];
    #pragma unroll
    for (int i = 1; i < 8; i++) r = fmaxf(r, s[i]);
    __syncthreads();
    return r;
}
__device__ __forceinline__ float blockSum256(float v) {
    __shared__ float s[8];
    #pragma unroll
    for (int o = 16; o > 0; o >>= 1) v += __shfl_xor_sync(0xffffffffu, v, o);
    if ((threadIdx.x & 31) == 0) s[threadIdx.x >> 5] = v;
    __syncthreads();
    float r = s[0];
    #pragma unroll
    for (int i = 1; i < 8; i++) r += s[i];
    __syncthreads();
    return r;
}

// ============================================================================
// Kernel 1: L2-normalize concat(lb_feat, anchor) -> fp16 hi/lo split
// ============================================================================
__global__ void normalize_kernel(const float* __restrict__ lb_feat,
                                 const float* __restrict__ anchor) {
    const int row = blockIdx.x;
    const int t = threadIdx.x;
    const float* src = (row < NL) ? lb_feat + (size_t)row * D
                                  : anchor + (size_t)(row - NL) * D;
    float4 v = ((const float4*)src)[t];
    float ss = v.x * v.x + v.y * v.y + v.z * v.z + v.w * v.w;
    #pragma unroll
    for (int o = 16; o > 0; o >>= 1) ss += __shfl_xor_sync(0xffffffffu, ss, o);
    __shared__ float ws[4];
    if ((t & 31) == 0) ws[t >> 5] = ss;
    __syncthreads();
    float tot = ws[0] + ws[1] + ws[2] + ws[3];
    float sc = 1.0f / fmaxf(sqrtf(tot), 1e-12f);
    float n0 = v.x * sc, n1 = v.y * sc, n2 = v.z * sc, n3 = v.w * sc;
    __half h0 = __float2half_rn(n0), h1 = __float2half_rn(n1);
    __half h2 = __float2half_rn(n2), h3 = __float2half_rn(n3);
    __half l0 = __float2half_rn(n0 - __half2float(h0));
    __half l1 = __float2half_rn(n1 - __half2float(h1));
    __half l2 = __float2half_rn(n2 - __half2float(h2));
    __half l3 = __float2half_rn(n3 - __half2float(h3));
    __half2 hA = __halves2half2(h0, h1), hB = __halves2half2(h2, h3);
    __half2 lA = __halves2half2(l0, l1), lB = __halves2half2(l2, l3);
    uint2 hp, lp;
    hp.x = *(uint32_t*)&hA; hp.y = *(uint32_t*)&hB;
    lp.x = *(uint32_t*)&lA; lp.y = *(uint32_t*)&lB;
    ((uint2*)(g_nh + (size_t)row * D))[t] = hp;
    ((uint2*)(g_nl + (size_t)row * D))[t] = lp;
}

// ============================================================================
// Kernel 2: class_val = concat(lb_one_hot, softmax(logits_x_ulb_1)) -> g_cv
// ============================================================================
__global__ void classval_kernel(const float* __restrict__ lb_one_hot,
                                const float* __restrict__ logits) {
    const int row = blockIdx.x;
    const int t = threadIdx.x;
    float* dst = g_cv + (size_t)row * CC;
    if (row < NL) {
        const float* src = lb_one_hot + (size_t)row * CC;
        for (int j = t; j < CC; j += 256) dst[j] = src[j];
        return;
    }
    const float* src = logits + (size_t)(row - NL) * CC;
    float v[4];
    float mx = -1e30f;
    #pragma unroll
    for (int q = 0; q < 4; q++) {
        int j = t + q * 256;
        v[q] = (j < CC) ? src[j] : -1e30f;
        mx = fmaxf(mx, v[q]);
    }
    mx = blockMax256(mx);
    float sum = 0.f;
    #pragma unroll
    for (int q = 0; q < 4; q++) {
        int j = t + q * 256;
        float e = (j < CC) ? fast_expf(v[q] - mx) : 0.f;
        v[q] = e;
        sum += e;
    }
    sum = blockSum256(sum);
    float inv = 1.0f / sum;
    #pragma unroll
    for (int q = 0; q < 4; q++) {
        int j = t + q * 256;
        if (j < CC) dst[j] = v[q] * inv;
    }
}

// ============================================================================
// Kernel 3: transpose g_cv [8192 x 1000] fp32 -> g_cvT [1024 x 8192] fp16
// ============================================================================
__global__ void transpose_cv_kernel() {
    __shared__ float s[32][33];
    const int k0 = blockIdx.x * 32, c0 = blockIdx.y * 32;
    const int tx = threadIdx.x & 31, ty = threadIdx.x >> 5;
    #pragma unroll
    for (int q = 0; q < 4; q++) {
        int k = k0 + ty + q * 8, c = c0 + tx;
        s[ty + q * 8][tx] = (c < CC) ? g_cv[(size_t)k * CC + c] : 0.f;
    }
    __syncthreads();
    #pragma unroll
    for (int q = 0; q < 4; q++) {
        int c = c0 + ty + q * 8, k = k0 + tx;
        g_cvT[(size_t)c * NT + k] = __float2half_rn(s[tx][ty + q * 8]);
    }
}

// ============================================================================
// Kernel 4: GEMM1 (HMMA): dot = n@n^T via fp16 hi/lo 3-pass; E = exp(10*dot)
// -> g_E fp16. Block 128x128, kc=64, 8 warps (2x4), warp tile 64x32.
// SMEM/stage: Ah 16KB | Al 16KB | Bh 16KB | Bl 16KB = 64KB; 2 stages = 128KB.
// ============================================================================
__device__ __forceinline__ void g1_load(uint32_t sb, int s, int c, int i0, int j0, int t) {
    #pragma unroll
    for (int q = 0; q < 4; q++) {
        int u = t + q * 256, row = u >> 3, seg = u & 7;
        uint32_t so = smoff(row, seg);
        uint32_t dA = sb + s * 65536 + so;
        size_t ga = ((size_t)(i0 + row) * D + c * 64 + seg * 8) * 2;
        size_t gb = ((size_t)(j0 + row) * D + c * 64 + seg * 8) * 2;
        CP16(dA,         (const char*)g_nh + ga);
        CP16(dA + 16384, (const char*)g_nl + ga);
        CP16(dA + 32768, (const char*)g_nh + gb);
        CP16(dA + 49152, (const char*)g_nl + gb);
    }
}

__global__ __launch_bounds__(256) void gemm1_kernel() {
    extern __shared__ char smem[];
    const uint32_t sb = smem_u32(smem);
    const int t = threadIdx.x, lane = t & 31, w = t >> 5;
    const int wm = w >> 2, wn = w & 3;
    const int i0 = blockIdx.y * 128, j0 = blockIdx.x * 128;

    float acc[4][4][4];
    #pragma unroll
    for (int a = 0; a < 4; a++)
        #pragma unroll
        for (int b = 0; b < 4; b++)
            #pragma unroll
            for (int cth = 0; cth < 4; cth++) acc[a][b][cth] = 0.f;

    const int rA = wm * 64 + (lane & 15);
    const int sA = lane >> 4;
    const int rB = wn * 32 + ((lane >> 4) & 1) * 8 + (lane & 7);
    const int sB = (lane >> 3) & 1;

    g1_load(sb, 0, 0, i0, j0, t);
    CP_COMMIT();

    for (int c = 0; c < 8; c++) {
        const int s = c & 1;
        if (c < 7) { g1_load(sb, s ^ 1, c + 1, i0, j0, t); CP_COMMIT(); CP_WAIT1(); }
        else       { CP_WAIT0(); }
        __syncthreads();
        const uint32_t bAh = sb + s * 65536;
        const uint32_t bAl = bAh + 16384, bBh = bAh + 32768, bBl = bAh + 49152;
        #pragma unroll
        for (int kk = 0; kk < 4; kk++) {
            uint32_t ah[4][4], al[4][4], bh[8], bl[8];
            #pragma unroll
            for (int mt = 0; mt < 4; mt++)
                ldm_x4(ah[mt], bAh + smoff(rA + mt * 16, 2 * kk + sA));
            #pragma unroll
            for (int jj = 0; jj < 2; jj++)
                ldm_x4(bh + jj * 4, bBh + smoff(rB + jj * 16, 2 * kk + sB));
            #pragma unroll
            for (int mt = 0; mt < 4; mt++)
                #pragma unroll
                for (int nt = 0; nt < 4; nt++)
                    mma16816(acc[mt][nt], ah[mt], bh + nt * 2);
            #pragma unroll
            for (int jj = 0; jj < 2; jj++)
                ldm_x4(bl + jj * 4, bBl + smoff(rB + jj * 16, 2 * kk + sB));
            #pragma unroll
            for (int mt = 0; mt < 4; mt++)
                #pragma unroll
                for (int nt = 0; nt < 4; nt++)
                    mma16816(acc[mt][nt], ah[mt], bl + nt * 2);
            #pragma unroll
            for (int mt = 0; mt < 4; mt++)
                ldm_x4(al[mt], bAl + smoff(rA + mt * 16, 2 * kk + sA));
            #pragma unroll
            for (int mt = 0; mt < 4; mt++)
                #pragma unroll
                for (int nt = 0; nt < 4; nt++)
                    mma16816(acc[mt][nt], al[mt], bh + nt * 2);
        }
        __syncthreads();
    }

    // Epilogue: E = exp(10*acc) -> fp16
    const int g = lane >> 2, cq = lane & 3;
    #pragma unroll
    for (int mt = 0; mt < 4; mt++) {
        #pragma unroll
        for (int h = 0; h < 2; h++) {
            const int row = i0 + wm * 64 + mt * 16 + g + h * 8;
            __half* erow = g_E + (size_t)row * NT + j0 + wn * 32;
            #pragma unroll
            for (int nt = 0; nt < 4; nt++) {
                float e0 = fast_expf(acc[mt][nt][2 * h] * 10.f);
                float e1 = fast_expf(acc[mt][nt][2 * h + 1] * 10.f);
                __half2 p = __floats2half2_rn(e0, e1);
                *(__half2*)(erow + nt * 8 + cq * 2) = p;
            }
        }
    }
}

// ============================================================================
// Kernel 5: rowsum of E (fp32) -> g_rsum
// ============================================================================
__global__ void rowsum_kernel() {
    const int row = blockIdx.x, t = threadIdx.x;
    const uint4* p = (const uint4*)(g_E + (size_t)row * NT);
    float sum = 0.f;
    #pragma unroll
    for (int q = 0; q < 4; q++) {
        uint4 u = p[t + q * 256];
        const __half2* h = (const __half2*)&u;
        #pragma unroll
        for (int k = 0; k < 4; k++) {
            float2 f = __half22float2(h[k]);
            sum += f.x + f.y;
        }
    }
    sum = blockSum256(sum);
    if (t == 0) g_rsum[row] = sum;
}

// ============================================================================
// Kernel 6: GEMM2 (HMMA): out = (E @ cvT^T) / rsum -> d_out fp32
// Block 128x128, K=8192 (128 chunks of 64). SMEM/stage: A 16KB | B 16KB.
// ============================================================================
__device__ __forceinline__ void g2_load(uint32_t sb, int s, int c, int i0, int j0, int t) {
    #pragma unroll
    for (int q = 0; q < 4; q++) {
        int u = t + q * 256, row = u >> 3, seg = u & 7;
        uint32_t so = smoff(row, seg);
        uint32_t dA = sb + s * 32768 + so;
        size_t ga = ((size_t)(i0 + row) * NT + c * 64 + seg * 8) * 2;
        size_t gb = ((size_t)(j0 + row) * NT + c * 64 + seg * 8) * 2;
        CP16(dA,         (const char*)g_E + ga);
        CP16(dA + 16384, (const char*)g_cvT + gb);
    }
}

__global__ __launch_bounds__(256) void gemm2_kernel(float* __restrict__ out) {
    extern __shared__ char smem[];
    const uint32_t sb = smem_u32(smem);
    const int t = threadIdx.x, lane = t & 31, w = t >> 5;
    const int wm = w >> 2, wn = w & 3;
    const int i0 = blockIdx.y * 128, j0 = blockIdx.x * 128;

    float acc[4][4][4];
    #pragma unroll
    for (int a = 0; a < 4; a++)
        #pragma unroll
        for (int b = 0; b < 4; b++)
            #pragma unroll
            for (int cth = 0; cth < 4; cth++) acc[a][b][cth] = 0.f;

    const int rA = wm * 64 + (lane & 15);
    const int sA = lane >> 4;
    const int rB = wn * 32 + ((lane >> 4) & 1) * 8 + (lane & 7);
    const int sB = (lane >> 3) & 1;

    g2_load(sb, 0, 0, i0, j0, t);
    CP_COMMIT();

    for (int c = 0; c < 128; c++) {
        const int s = c & 1;
        if (c < 127) { g2_load(sb, s ^ 1, c + 1, i0, j0, t); CP_COMMIT(); CP_WAIT1(); }
        else         { CP_WAIT0(); }
        __syncthreads();
        const uint32_t bA = sb + s * 32768;
        const uint32_t bB = bA + 16384;
        #pragma unroll
        for (int kk = 0; kk < 4; kk++) {
            uint32_t af[4][4], bf[8];
            #pragma unroll
            for (int mt = 0; mt < 4; mt++)
                ldm_x4(af[mt], bA + smoff(rA + mt * 16, 2 * kk + sA));
            #pragma unroll
            for (int jj = 0; jj < 2; jj++)
                ldm_x4(bf + jj * 4, bB + smoff(rB + jj * 16, 2 * kk + sB));
            #pragma unroll
            for (int mt = 0; mt < 4; mt++)
                #pragma unroll
                for (int nt = 0; nt < 4; nt++)
                    mma16816(acc[mt][nt], af[mt], bf + nt * 2);
        }
        __syncthreads();
    }

    const int g = lane >> 2, cq = lane & 3;
    #pragma unroll
    for (int mt = 0; mt < 4; mt++) {
        #pragma unroll
        for (int h = 0; h < 2; h++) {
            const int row = i0 + wm * 64 + mt * 16 + g + h * 8;
            const float inv = 1.0f / g_rsum[row];
            float* crow = out + (size_t)row * CC;
            #pragma unroll
            for (int nt = 0; nt < 4; nt++) {
                int col = j0 + wn * 32 + nt * 8 + cq * 2;
                if (col < CC) {
                    float2 v = make_float2(acc[mt][nt][2 * h] * inv,
                                           acc[mt][nt][2 * h + 1] * inv);
                    *(float2*)(crow + col) = v;
                }
            }
        }
    }
}

// ============================================================================
// Launch. Output layout (float32):
//   [0)         anchor_feat    3145728
//   [3145728)   positive_feat  3145728
//   [6291456)   lb_feat        1048576
//   [7340032)   lb_one_hot     2048000
//   [9388032)   new_lb||new_ulb1  8192000 (contiguous 8192x1000)
//   [17580032)  logits_x_ulb_2 6144000
// ============================================================================
extern "C" void kernel_launch(void* const* d_in, const int* in_sizes, int n_in,
                              void* d_out, int out_size) {
    const float* anchor   = (const float*)d_in[0];
    const float* positive = (const float*)d_in[1];
    const float* lb_feat  = (const float*)d_in[2];
    const float* lb_oh    = (const float*)d_in[3];
    const float* lg_ulb1  = (const float*)d_in[5];
    const float* lg_ulb2  = (const float*)d_in[6];
    float* out = (float*)d_out;

    cudaMemcpyAsync(out,            anchor,   (size_t)NU * D  * sizeof(float), cudaMemcpyDeviceToDevice, 0);
    cudaMemcpyAsync(out + 3145728,  positive, (size_t)NU * D  * sizeof(float), cudaMemcpyDeviceToDevice, 0);
    cudaMemcpyAsync(out + 6291456,  lb_feat,  (size_t)NL * D  * sizeof(float), cudaMemcpyDeviceToDevice, 0);
    cudaMemcpyAsync(out + 7340032,  lb_oh,    (size_t)NL * CC * sizeof(float), cudaMemcpyDeviceToDevice, 0);
    cudaMemcpyAsync(out + 17580032, lg_ulb2,  (size_t)NU * CC * sizeof(float), cudaMemcpyDeviceToDevice, 0);

    normalize_kernel<<<NT, 128>>>(lb_feat, anchor);
    classval_kernel<<<NT, 256>>>(lb_oh, lg_ulb1);
    transpose_cv_kernel<<<dim3(NT / 32, CCP / 32), 256>>>();

    cudaFuncSetAttribute(gemm1_kernel, cudaFuncAttributeMaxDynamicSharedMemorySize, 131072);
    cudaFuncSetAttribute(gemm2_kernel, cudaFuncAttributeMaxDynamicSharedMemorySize, 65536);

    gemm1_kernel<<<dim3(64, 64), 256, 131072>>>();
    rowsum_kernel<<<NT, 256>>>();
    gemm2_kernel<<<dim3(8, 64), 256, 65536>>>(out + 9388032);
}

// round 4
// speedup vs baseline: 8.6149x; 1.3479x over previous
#include <cuda_runtime.h>
#include <cuda_fp16.h>
#include <cstdint>

// Problem sizes
static constexpr int NL = 2048;
static constexpr int NU = 6144;
static constexpr int NT = 8192;   // NL + NU
static constexpr int D  = 512;
static constexpr int CC = 1000;
static constexpr int CCP = 1024;  // padded classes

// Scratch (device globals; no allocation allowed)
__device__ __half g_nh[(size_t)NT * D];      // normalized feats hi fp16 (8MB)
__device__ __half g_nl[(size_t)NT * D];      // normalized feats lo fp16 (8MB)
__device__ float  g_cv[(size_t)NT * CC];     // class_val fp32 (32.8MB)
__device__ __half g_cvT[(size_t)CCP * NT];   // class_val^T fp16 (16.8MB)
__device__ __half g_E[(size_t)NT * NT];      // exp(S) fp16 (134MB)
__device__ float  g_rsum[NT];                // softmax denominators
__device__ int    g_label[NL];               // argmax of lb_one_hot rows

// ============================================================================
// Helpers
// ============================================================================
__device__ __forceinline__ uint32_t smem_u32(const void* p) {
    uint32_t a;
    asm("{ .reg .u64 t; cvta.to.shared.u64 t, %1; cvt.u32.u64 %0, t; }" : "=r"(a) : "l"(p));
    return a;
}
// swizzled byte offset inside a tile of 128B rows (8 x 16B segments per row)
__device__ __forceinline__ uint32_t smoff(int row, int seg) {
    return (uint32_t)(row * 128 + ((seg ^ (row & 7)) << 4));
}
#define CP16(dst, src) \
    asm volatile("cp.async.cg.shared.global [%0], [%1], 16;" :: "r"(dst), "l"(src) : "memory")
#define CP_COMMIT() asm volatile("cp.async.commit_group;" ::: "memory")
#define CP_WAIT1() asm volatile("cp.async.wait_group 1;" ::: "memory")
#define CP_WAIT0() asm volatile("cp.async.wait_group 0;" ::: "memory")

__device__ __forceinline__ void ldm_x4(uint32_t* r, uint32_t addr) {
    asm volatile("ldmatrix.sync.aligned.m8n8.x4.shared.b16 {%0,%1,%2,%3}, [%4];"
                 : "=r"(r[0]), "=r"(r[1]), "=r"(r[2]), "=r"(r[3]) : "r"(addr));
}
__device__ __forceinline__ void mma16816(float* d, const uint32_t* a, const uint32_t* b) {
    asm volatile(
        "mma.sync.aligned.m16n8k16.row.col.f32.f16.f16.f32 "
        "{%0,%1,%2,%3}, {%4,%5,%6,%7}, {%8,%9}, {%0,%1,%2,%3};"
        : "+f"(d[0]), "+f"(d[1]), "+f"(d[2]), "+f"(d[3])
        : "r"(a[0]), "r"(a[1]), "r"(a[2]), "r"(a[3]), "r"(b[0]), "r"(b[1]));
}

// FMA-only exp, valid for |x| <= ~11, rel err < 2e-7
__device__ __forceinline__ float fast_expf(float x) {
    float z = x * 1.4426950408889634f;
    float n = rintf(z);
    float r = fmaf(n, -0.6931471824645996f, x);
    r = fmaf(n, 1.9046542743e-9f, r);
    float p = 1.3888889225e-3f;
    p = fmaf(p, r, 8.3333337680e-3f);
    p = fmaf(p, r, 4.1666667908e-2f);
    p = fmaf(p, r, 1.6666667163e-1f);
    p = fmaf(p, r, 5.0e-1f);
    p = fmaf(p, r, 1.0f);
    p = fmaf(p, r, 1.0f);
    float s = __int_as_float(((int)n + 127) << 23);
    return p * s;
}

__device__ __forceinline__ float blockMax256(float v) {
    __shared__ float s[8];
    #pragma unroll
    for (int o = 16; o > 0; o >>= 1) v = fmaxf(v, __shfl_xor_sync(0xffffffffu, v, o));
    if ((threadIdx.x & 31) == 0) s[threadIdx.x >> 5] = v;
    __syncthreads();
    float r = s[0];
    #pragma unroll
    for (int i = 1; i < 8; i++) r = fmaxf(r, s[i]);
    __syncthreads();
    return r;
}
__device__ __forceinline__ float blockSum256(float v) {
    __shared__ float s[8];
    #pragma unroll
    for (int o = 16; o > 0; o >>= 1) v += __shfl_xor_sync(0xffffffffu, v, o);
    if ((threadIdx.x & 31) == 0) s[threadIdx.x >> 5] = v;
    __syncthreads();
    float r = s[0];
    #pragma unroll
    for (int i = 1; i < 8; i++) r += s[i];
    __syncthreads();
    return r;
}

// ============================================================================
// Kernel 1: L2-normalize concat(lb_feat, anchor) -> fp16 hi/lo split
// ============================================================================
__global__ void normalize_kernel(const float* __restrict__ lb_feat,
                                 const float* __restrict__ anchor) {
    const int row = blockIdx.x;
    const int t = threadIdx.x;
    const float* src = (row < NL) ? lb_feat + (size_t)row * D
                                  : anchor + (size_t)(row - NL) * D;
    float4 v = ((const float4*)src)[t];
    float ss = v.x * v.x + v.y * v.y + v.z * v.z + v.w * v.w;
    #pragma unroll
    for (int o = 16; o > 0; o >>= 1) ss += __shfl_xor_sync(0xffffffffu, ss, o);
    __shared__ float ws[4];
    if ((t & 31) == 0) ws[t >> 5] = ss;
    __syncthreads();
    float tot = ws[0] + ws[1] + ws[2] + ws[3];
    float sc = 1.0f / fmaxf(sqrtf(tot), 1e-12f);
    float n0 = v.x * sc, n1 = v.y * sc, n2 = v.z * sc, n3 = v.w * sc;
    __half h0 = __float2half_rn(n0), h1 = __float2half_rn(n1);
    __half h2 = __float2half_rn(n2), h3 = __float2half_rn(n3);
    __half l0 = __float2half_rn(n0 - __half2float(h0));
    __half l1 = __float2half_rn(n1 - __half2float(h1));
    __half l2 = __float2half_rn(n2 - __half2float(h2));
    __half l3 = __float2half_rn(n3 - __half2float(h3));
    __half2 hA = __halves2half2(h0, h1), hB = __halves2half2(h2, h3);
    __half2 lA = __halves2half2(l0, l1), lB = __halves2half2(l2, l3);
    uint2 hp, lp;
    hp.x = *(uint32_t*)&hA; hp.y = *(uint32_t*)&hB;
    lp.x = *(uint32_t*)&lA; lp.y = *(uint32_t*)&lB;
    ((uint2*)(g_nh + (size_t)row * D))[t] = hp;
    ((uint2*)(g_nl + (size_t)row * D))[t] = lp;
}

// ============================================================================
// Kernel 2: class_val = concat(lb_one_hot, softmax(logits_x_ulb_1)) -> g_cv
// ============================================================================
__global__ void classval_kernel(const float* __restrict__ lb_one_hot,
                                const float* __restrict__ logits) {
    const int row = blockIdx.x;
    const int t = threadIdx.x;
    float* dst = g_cv + (size_t)row * CC;
    if (row < NL) {
        const float* src = lb_one_hot + (size_t)row * CC;
        for (int j = t; j < CC; j += 256) dst[j] = src[j];
        return;
    }
    const float* src = logits + (size_t)(row - NL) * CC;
    float v[4];
    float mx = -1e30f;
    #pragma unroll
    for (int q = 0; q < 4; q++) {
        int j = t + q * 256;
        v[q] = (j < CC) ? src[j] : -1e30f;
        mx = fmaxf(mx, v[q]);
    }
    mx = blockMax256(mx);
    float sum = 0.f;
    #pragma unroll
    for (int q = 0; q < 4; q++) {
        int j = t + q * 256;
        float e = (j < CC) ? fast_expf(v[q] - mx) : 0.f;
        v[q] = e;
        sum += e;
    }
    sum = blockSum256(sum);
    float inv = 1.0f / sum;
    #pragma unroll
    for (int q = 0; q < 4; q++) {
        int j = t + q * 256;
        if (j < CC) dst[j] = v[q] * inv;
    }
}

// ============================================================================
// Kernel 3: transpose g_cv [8192 x 1000] fp32 -> g_cvT [1024 x 8192] fp16
// (only the unlabeled K-range [2048,8192) is consumed by GEMM2, but the full
//  transpose is cheap and keeps indexing simple)
// ============================================================================
__global__ void transpose_cv_kernel() {
    __shared__ float s[32][33];
    const int k0 = blockIdx.x * 32, c0 = blockIdx.y * 32;
    const int tx = threadIdx.x & 31, ty = threadIdx.x >> 5;
    #pragma unroll
    for (int q = 0; q < 4; q++) {
        int k = k0 + ty + q * 8, c = c0 + tx;
        s[ty + q * 8][tx] = (c < CC) ? g_cv[(size_t)k * CC + c] : 0.f;
    }
    __syncthreads();
    #pragma unroll
    for (int q = 0; q < 4; q++) {
        int c = c0 + ty + q * 8, k = k0 + tx;
        g_cvT[(size_t)c * NT + k] = __float2half_rn(s[tx][ty + q * 8]);
    }
}

// ============================================================================
// Kernel 3b: labels = argmax(lb_one_hot) (exact one-hot -> find the 1.0)
// ============================================================================
__global__ void labels_kernel(const float* __restrict__ lb_one_hot) {
    const int row = blockIdx.x, t = threadIdx.x;
    const float* src = lb_one_hot + (size_t)row * CC;
    #pragma unroll
    for (int q = 0; q < 4; q++) {
        int c = t + q * 256;
        if (c < CC && src[c] > 0.5f) g_label[row] = c;
    }
}

// ============================================================================
// Kernel 4: GEMM1 (HMMA): dot = n@n^T via fp16 hi/lo 3-pass; E = exp(10*dot)
// SYMMETRIC: only upper-triangular 128x128 blocks (bi <= bj); off-diagonal
// blocks also write the transposed tile (staged through SMEM).
// Block 128x128, kc=64, 8 warps (2x4), warp tile 64x32.
// SMEM/stage: Ah 16KB | Al 16KB | Bh 16KB | Bl 16KB = 64KB; 2 stages = 128KB.
// ============================================================================
__device__ __forceinline__ void g1_load(uint32_t sb, int s, int c, int i0, int j0, int t) {
    #pragma unroll
    for (int q = 0; q < 4; q++) {
        int u = t + q * 256, row = u >> 3, seg = u & 7;
        uint32_t so = smoff(row, seg);
        uint32_t dA = sb + s * 65536 + so;
        size_t ga = ((size_t)(i0 + row) * D + c * 64 + seg * 8) * 2;
        size_t gb = ((size_t)(j0 + row) * D + c * 64 + seg * 8) * 2;
        CP16(dA,         (const char*)g_nh + ga);
        CP16(dA + 16384, (const char*)g_nl + ga);
        CP16(dA + 32768, (const char*)g_nh + gb);
        CP16(dA + 49152, (const char*)g_nl + gb);
    }
}

static constexpr int NB = NT / 128;  // 64 blocks per dim
static constexpr int TP = 136;       // transpose-stage pitch in halves (16B-aligned rows)

__global__ __launch_bounds__(256) void gemm1_kernel() {
    extern __shared__ char smem[];
    const uint32_t sb = smem_u32(smem);
    const int t = threadIdx.x, lane = t & 31, w = t >> 5;
    const int wm = w >> 2, wn = w & 3;

    // triangular decode: blockIdx.x -> (bi, bj), bi <= bj
    int bi = 0, rem = blockIdx.x;
    while (rem >= NB - bi) { rem -= NB - bi; bi++; }
    const int bj = bi + rem;
    const int i0 = bi * 128, j0 = bj * 128;

    float acc[4][4][4];
    #pragma unroll
    for (int a = 0; a < 4; a++)
        #pragma unroll
        for (int b = 0; b < 4; b++)
            #pragma unroll
            for (int cth = 0; cth < 4; cth++) acc[a][b][cth] = 0.f;

    const int rA = wm * 64 + (lane & 15);
    const int sA = lane >> 4;
    const int rB = wn * 32 + ((lane >> 4) & 1) * 8 + (lane & 7);
    const int sB = (lane >> 3) & 1;

    g1_load(sb, 0, 0, i0, j0, t);
    CP_COMMIT();

    for (int c = 0; c < 8; c++) {
        const int s = c & 1;
        if (c < 7) { g1_load(sb, s ^ 1, c + 1, i0, j0, t); CP_COMMIT(); CP_WAIT1(); }
        else       { CP_WAIT0(); }
        __syncthreads();
        const uint32_t bAh = sb + s * 65536;
        const uint32_t bAl = bAh + 16384, bBh = bAh + 32768, bBl = bAh + 49152;
        #pragma unroll
        for (int kk = 0; kk < 4; kk++) {
            uint32_t ah[4][4], al[4][4], bh[8], bl[8];
            #pragma unroll
            for (int mt = 0; mt < 4; mt++)
                ldm_x4(ah[mt], bAh + smoff(rA + mt * 16, 2 * kk + sA));
            #pragma unroll
            for (int jj = 0; jj < 2; jj++)
                ldm_x4(bh + jj * 4, bBh + smoff(rB + jj * 16, 2 * kk + sB));
            #pragma unroll
            for (int mt = 0; mt < 4; mt++)
                #pragma unroll
                for (int nt = 0; nt < 4; nt++)
                    mma16816(acc[mt][nt], ah[mt], bh + nt * 2);
            #pragma unroll
            for (int jj = 0; jj < 2; jj++)
                ldm_x4(bl + jj * 4, bBl + smoff(rB + jj * 16, 2 * kk + sB));
            #pragma unroll
            for (int mt = 0; mt < 4; mt++)
                #pragma unroll
                for (int nt = 0; nt < 4; nt++)
                    mma16816(acc[mt][nt], ah[mt], bl + nt * 2);
            #pragma unroll
            for (int mt = 0; mt < 4; mt++)
                ldm_x4(al[mt], bAl + smoff(rA + mt * 16, 2 * kk + sA));
            #pragma unroll
            for (int mt = 0; mt < 4; mt++)
                #pragma unroll
                for (int nt = 0; nt < 4; nt++)
                    mma16816(acc[mt][nt], al[mt], bh + nt * 2);
        }
        __syncthreads();
    }
    // After the final __syncthreads(), no warp reads the stage buffers again:
    // safe to reuse smem for the transpose staging below.

    // Epilogue: E = exp(10*acc) -> fp16. Normal tile + (off-diag) transposed.
    const int g = lane >> 2, cq = lane & 3;
    __half* sT = (__half*)smem;  // pitch TP halves
    #pragma unroll
    for (int mt = 0; mt < 4; mt++) {
        #pragma unroll
        for (int h = 0; h < 2; h++) {
            const int rl = wm * 64 + mt * 16 + g + h * 8;      // local row
            __half* erow = g_E + (size_t)(i0 + rl) * NT + j0 + wn * 32;
            #pragma unroll
            for (int nt = 0; nt < 4; nt++) {
                float e0 = fast_expf(acc[mt][nt][2 * h] * 10.f);
                float e1 = fast_expf(acc[mt][nt][2 * h + 1] * 10.f);
                __half2 p = __floats2half2_rn(e0, e1);
                const int cl = wn * 32 + nt * 8 + cq * 2;       // local col
                *(__half2*)(erow + cl - wn * 32 + 0) = p;       // == erow + nt*8+cq*2
                if (bi != bj) {
                    sT[(size_t)cl * TP + rl]       = __low2half(p);
                    sT[(size_t)(cl + 1) * TP + rl] = __high2half(p);
                }
            }
        }
    }
    if (bi != bj) {
        __syncthreads();
        // coalesced write of transposed tile: 128 rows x 128 halves
        #pragma unroll
        for (int q = 0; q < 8; q++) {
            int u = t + q * 256;
            int row = u >> 4, seg = u & 15;
            *(uint4*)(g_E + (size_t)(j0 + row) * NT + i0 + seg * 8) =
                *(const uint4*)(sT + row * TP + seg * 8);
        }
    }
}

// ============================================================================
// Kernel 5: rowsum of E (fp32) -> g_rsum
// ============================================================================
__global__ void rowsum_kernel() {
    const int row = blockIdx.x, t = threadIdx.x;
    const uint4* p = (const uint4*)(g_E + (size_t)row * NT);
    float sum = 0.f;
    #pragma unroll
    for (int q = 0; q < 4; q++) {
        uint4 u = p[t + q * 256];
        const __half2* h = (const __half2*)&u;
        #pragma unroll
        for (int k = 0; k < 4; k++) {
            float2 f = __half22float2(h[k]);
            sum += f.x + f.y;
        }
    }
    sum = blockSum256(sum);
    if (t == 0) g_rsum[row] = sum;
}

// ============================================================================
// Kernel 6: GEMM2 (HMMA): out = (E[:,2048:] @ cvT[:,2048:]^T) / rsum
// (labeled K-range handled by scatter_kernel). K = 6144 (96 chunks of 64).
// ============================================================================
__device__ __forceinline__ void g2_load(uint32_t sb, int s, int c, int i0, int j0, int t) {
    #pragma unroll
    for (int q = 0; q < 4; q++) {
        int u = t + q * 256, row = u >> 3, seg = u & 7;
        uint32_t so = smoff(row, seg);
        uint32_t dA = sb + s * 32768 + so;
        size_t ga = ((size_t)(i0 + row) * NT + NL + c * 64 + seg * 8) * 2;
        size_t gb = ((size_t)(j0 + row) * NT + NL + c * 64 + seg * 8) * 2;
        CP16(dA,         (const char*)g_E + ga);
        CP16(dA + 16384, (const char*)g_cvT + gb);
    }
}

__global__ __launch_bounds__(256) void gemm2_kernel(float* __restrict__ out) {
    extern __shared__ char smem[];
    const uint32_t sb = smem_u32(smem);
    const int t = threadIdx.x, lane = t & 31, w = t >> 5;
    const int wm = w >> 2, wn = w & 3;
    const int i0 = blockIdx.y * 128, j0 = blockIdx.x * 128;

    float acc[4][4][4];
    #pragma unroll
    for (int a = 0; a < 4; a++)
        #pragma unroll
        for (int b = 0; b < 4; b++)
            #pragma unroll
            for (int cth = 0; cth < 4; cth++) acc[a][b][cth] = 0.f;

    const int rA = wm * 64 + (lane & 15);
    const int sA = lane >> 4;
    const int rB = wn * 32 + ((lane >> 4) & 1) * 8 + (lane & 7);
    const int sB = (lane >> 3) & 1;

    g2_load(sb, 0, 0, i0, j0, t);
    CP_COMMIT();

    constexpr int NCH = (NT - NL) / 64;  // 96
    for (int c = 0; c < NCH; c++) {
        const int s = c & 1;
        if (c < NCH - 1) { g2_load(sb, s ^ 1, c + 1, i0, j0, t); CP_COMMIT(); CP_WAIT1(); }
        else             { CP_WAIT0(); }
        __syncthreads();
        const uint32_t bA = sb + s * 32768;
        const uint32_t bB = bA + 16384;
        #pragma unroll
        for (int kk = 0; kk < 4; kk++) {
            uint32_t af[4][4], bf[8];
            #pragma unroll
            for (int mt = 0; mt < 4; mt++)
                ldm_x4(af[mt], bA + smoff(rA + mt * 16, 2 * kk + sA));
            #pragma unroll
            for (int jj = 0; jj < 2; jj++)
                ldm_x4(bf + jj * 4, bB + smoff(rB + jj * 16, 2 * kk + sB));
            #pragma unroll
            for (int mt = 0; mt < 4; mt++)
                #pragma unroll
                for (int nt = 0; nt < 4; nt++)
                    mma16816(acc[mt][nt], af[mt], bf + nt * 2);
        }
        __syncthreads();
    }

    const int g = lane >> 2, cq = lane & 3;
    #pragma unroll
    for (int mt = 0; mt < 4; mt++) {
        #pragma unroll
        for (int h = 0; h < 2; h++) {
            const int row = i0 + wm * 64 + mt * 16 + g + h * 8;
            const float inv = 1.0f / g_rsum[row];
            float* crow = out + (size_t)row * CC;
            #pragma unroll
            for (int nt = 0; nt < 4; nt++) {
                int col = j0 + wn * 32 + nt * 8 + cq * 2;
                if (col < CC) {
                    float2 v = make_float2(acc[mt][nt][2 * h] * inv,
                                           acc[mt][nt][2 * h + 1] * inv);
                    *(float2*)(crow + col) = v;
                }
            }
        }
    }
}

// ============================================================================
// Kernel 7: scatter the labeled (one-hot) K-range into out.
// out[i][c] += (sum_{j<NL, label[j]==c} E[i][j]) / rsum[i]
// One block per row i. SMEM: 1000-float accumulator + 2048 labels.
// ============================================================================
__global__ __launch_bounds__(256) void scatter_kernel(float* __restrict__ out) {
    __shared__ float accum[CC];
    __shared__ int lab[NL];
    const int i = blockIdx.x, t = threadIdx.x;
    #pragma unroll
    for (int q = 0; q < 4; q++) {
        int c = t + q * 256;
        if (c < CC) accum[c] = 0.f;
    }
    #pragma unroll
    for (int q = 0; q < 8; q++) lab[t + q * 256] = g_label[t + q * 256];
    __syncthreads();
    // each thread: one uint4 = 8 halves of E[i, t*8 .. t*8+7]
    uint4 u = ((const uint4*)(g_E + (size_t)i * NT))[t];
    const __half2* h = (const __half2*)&u;
    const int j0 = t * 8;
    #pragma unroll
    for (int k = 0; k < 4; k++) {
        float2 f = __half22float2(h[k]);
        atomicAdd(&accum[lab[j0 + 2 * k]],     f.x);
        atomicAdd(&accum[lab[j0 + 2 * k + 1]], f.y);
    }
    __syncthreads();
    const float inv = 1.0f / g_rsum[i];
    float* crow = out + (size_t)i * CC;
    #pragma unroll
    for (int q = 0; q < 4; q++) {
        int c = t + q * 256;
        if (c < CC) crow[c] += accum[c] * inv;
    }
}

// ============================================================================
// Launch. Output layout (float32):
//   [0)         anchor_feat    3145728
//   [3145728)   positive_feat  3145728
//   [6291456)   lb_feat        1048576
//   [7340032)   lb_one_hot     2048000
//   [9388032)   new_lb||new_ulb1  8192000 (contiguous 8192x1000)
//   [17580032)  logits_x_ulb_2 6144000
// ============================================================================
extern "C" void kernel_launch(void* const* d_in, const int* in_sizes, int n_in,
                              void* d_out, int out_size) {
    const float* anchor   = (const float*)d_in[0];
    const float* positive = (const float*)d_in[1];
    const float* lb_feat  = (const float*)d_in[2];
    const float* lb_oh    = (const float*)d_in[3];
    const float* lg_ulb1  = (const float*)d_in[5];
    const float* lg_ulb2  = (const float*)d_in[6];
    float* out = (float*)d_out;

    cudaMemcpyAsync(out,            anchor,   (size_t)NU * D  * sizeof(float), cudaMemcpyDeviceToDevice, 0);
    cudaMemcpyAsync(out + 3145728,  positive, (size_t)NU * D  * sizeof(float), cudaMemcpyDeviceToDevice, 0);
    cudaMemcpyAsync(out + 6291456,  lb_feat,  (size_t)NL * D  * sizeof(float), cudaMemcpyDeviceToDevice, 0);
    cudaMemcpyAsync(out + 7340032,  lb_oh,    (size_t)NL * CC * sizeof(float), cudaMemcpyDeviceToDevice, 0);
    cudaMemcpyAsync(out + 17580032, lg_ulb2,  (size_t)NU * CC * sizeof(float), cudaMemcpyDeviceToDevice, 0);

    normalize_kernel<<<NT, 128>>>(lb_feat, anchor);
    classval_kernel<<<NT, 256>>>(lb_oh, lg_ulb1);
    transpose_cv_kernel<<<dim3(NT / 32, CCP / 32), 256>>>();
    labels_kernel<<<NL, 256>>>(lb_oh);

    cudaFuncSetAttribute(gemm1_kernel, cudaFuncAttributeMaxDynamicSharedMemorySize, 131072);
    cudaFuncSetAttribute(gemm2_kernel, cudaFuncAttributeMaxDynamicSharedMemorySize, 65536);

    gemm1_kernel<<<NB * (NB + 1) / 2, 256, 131072>>>();   // 2080 triangular blocks
    rowsum_kernel<<<NT, 256>>>();
    gemm2_kernel<<<dim3(8, 64), 256, 65536>>>(out + 9388032);
    scatter_kernel<<<NT, 256>>>(out + 9388032);
}

// round 5
// speedup vs baseline: 8.7363x; 1.0141x over previous
#include <cuda_runtime.h>
#include <cuda_fp16.h>
#include <cstdint>

// Problem sizes
static constexpr int NL = 2048;
static constexpr int NU = 6144;
static constexpr int NT = 8192;   // NL + NU
static constexpr int D  = 512;
static constexpr int CC = 1000;

// Scratch (device globals; no allocation allowed)
__device__ __half g_nh[(size_t)NT * D];      // normalized feats hi fp16 (8MB)
__device__ __half g_nl[(size_t)NT * D];      // normalized feats lo fp16 (8MB)
__device__ float  g_cv[(size_t)NT * CC];     // class_val fp32 (rows >= NL used)
__device__ __half g_cvT[(size_t)1024 * NT];  // class_val^T fp16 (cols >= NL used)
__device__ __half g_E[(size_t)NT * NT];      // exp(S) fp16 (134MB)
__device__ float  g_rsum[NT];                // softmax denominators (atomic-accumulated)
__device__ int    g_label[NL];               // argmax of lb_one_hot rows

// ============================================================================
// Helpers
// ============================================================================
__device__ __forceinline__ uint32_t smem_u32(const void* p) {
    uint32_t a;
    asm("{ .reg .u64 t; cvta.to.shared.u64 t, %1; cvt.u32.u64 %0, t; }" : "=r"(a) : "l"(p));
    return a;
}
// swizzled byte offset inside a tile of 128B rows (8 x 16B segments per row)
__device__ __forceinline__ uint32_t smoff(int row, int seg) {
    return (uint32_t)(row * 128 + ((seg ^ (row & 7)) << 4));
}
#define CP16(dst, src) \
    asm volatile("cp.async.cg.shared.global [%0], [%1], 16;" :: "r"(dst), "l"(src) : "memory")
#define CP_COMMIT() asm volatile("cp.async.commit_group;" ::: "memory")
#define CP_WAIT2() asm volatile("cp.async.wait_group 2;" ::: "memory")

__device__ __forceinline__ void ldm_x4(uint32_t* r, uint32_t addr) {
    asm volatile("ldmatrix.sync.aligned.m8n8.x4.shared.b16 {%0,%1,%2,%3}, [%4];"
                 : "=r"(r[0]), "=r"(r[1]), "=r"(r[2]), "=r"(r[3]) : "r"(addr));
}
__device__ __forceinline__ void mma16816(float* d, const uint32_t* a, const uint32_t* b) {
    asm volatile(
        "mma.sync.aligned.m16n8k16.row.col.f32.f16.f16.f32 "
        "{%0,%1,%2,%3}, {%4,%5,%6,%7}, {%8,%9}, {%0,%1,%2,%3};"
        : "+f"(d[0]), "+f"(d[1]), "+f"(d[2]), "+f"(d[3])
        : "r"(a[0]), "r"(a[1]), "r"(a[2]), "r"(a[3]), "r"(b[0]), "r"(b[1]));
}

// FMA-only exp, valid for |x| <= ~11, rel err < 2e-7
__device__ __forceinline__ float fast_expf(float x) {
    float z = x * 1.4426950408889634f;
    float n = rintf(z);
    float r = fmaf(n, -0.6931471824645996f, x);
    r = fmaf(n, 1.9046542743e-9f, r);
    float p = 1.3888889225e-3f;
    p = fmaf(p, r, 8.3333337680e-3f);
    p = fmaf(p, r, 4.1666667908e-2f);
    p = fmaf(p, r, 1.6666667163e-1f);
    p = fmaf(p, r, 5.0e-1f);
    p = fmaf(p, r, 1.0f);
    p = fmaf(p, r, 1.0f);
    float s = __int_as_float(((int)n + 127) << 23);
    return p * s;
}

__device__ __forceinline__ float blockMax256(float v) {
    __shared__ float s[8];
    #pragma unroll
    for (int o = 16; o > 0; o >>= 1) v = fmaxf(v, __shfl_xor_sync(0xffffffffu, v, o));
    if ((threadIdx.x & 31) == 0) s[threadIdx.x >> 5] = v;
    __syncthreads();
    float r = s[0];
    #pragma unroll
    for (int i = 1; i < 8; i++) r = fmaxf(r, s[i]);
    __syncthreads();
    return r;
}
__device__ __forceinline__ float blockSum256(float v) {
    __shared__ float s[8];
    #pragma unroll
    for (int o = 16; o > 0; o >>= 1) v += __shfl_xor_sync(0xffffffffu, v, o);
    if ((threadIdx.x & 31) == 0) s[threadIdx.x >> 5] = v;
    __syncthreads();
    float r = s[0];
    #pragma unroll
    for (int i = 1; i < 8; i++) r += s[i];
    __syncthreads();
    return r;
}

// ============================================================================
// Kernel 1: L2-normalize concat(lb_feat, anchor) -> fp16 hi/lo split
// ============================================================================
__global__ void normalize_kernel(const float* __restrict__ lb_feat,
                                 const float* __restrict__ anchor) {
    const int row = blockIdx.x;
    const int t = threadIdx.x;
    const float* src = (row < NL) ? lb_feat + (size_t)row * D
                                  : anchor + (size_t)(row - NL) * D;
    float4 v = ((const float4*)src)[t];
    float ss = v.x * v.x + v.y * v.y + v.z * v.z + v.w * v.w;
    #pragma unroll
    for (int o = 16; o > 0; o >>= 1) ss += __shfl_xor_sync(0xffffffffu, ss, o);
    __shared__ float ws[4];
    if ((t & 31) == 0) ws[t >> 5] = ss;
    __syncthreads();
    float tot = ws[0] + ws[1] + ws[2] + ws[3];
    float sc = 1.0f / fmaxf(sqrtf(tot), 1e-12f);
    float n0 = v.x * sc, n1 = v.y * sc, n2 = v.z * sc, n3 = v.w * sc;
    __half h0 = __float2half_rn(n0), h1 = __float2half_rn(n1);
    __half h2 = __float2half_rn(n2), h3 = __float2half_rn(n3);
    __half l0 = __float2half_rn(n0 - __half2float(h0));
    __half l1 = __float2half_rn(n1 - __half2float(h1));
    __half l2 = __float2half_rn(n2 - __half2float(h2));
    __half l3 = __float2half_rn(n3 - __half2float(h3));
    __half2 hA = __halves2half2(h0, h1), hB = __halves2half2(h2, h3);
    __half2 lA = __halves2half2(l0, l1), lB = __halves2half2(l2, l3);
    uint2 hp, lp;
    hp.x = *(uint32_t*)&hA; hp.y = *(uint32_t*)&hB;
    lp.x = *(uint32_t*)&lA; lp.y = *(uint32_t*)&lB;
    ((uint2*)(g_nh + (size_t)row * D))[t] = hp;
    ((uint2*)(g_nl + (size_t)row * D))[t] = lp;
}

// ============================================================================
// Kernel 2: rows < NL: extract label (argmax of one-hot).
//           rows >= NL: softmax(logits_x_ulb_1) -> g_cv.
// ============================================================================
__global__ void classval_kernel(const float* __restrict__ lb_one_hot,
                                const float* __restrict__ logits) {
    const int row = blockIdx.x;
    const int t = threadIdx.x;
    if (row < NL) {
        const float* src = lb_one_hot + (size_t)row * CC;
        #pragma unroll
        for (int q = 0; q < 4; q++) {
            int c = t + q * 256;
            if (c < CC && src[c] > 0.5f) g_label[row] = c;
        }
        return;
    }
    const float* src = logits + (size_t)(row - NL) * CC;
    float* dst = g_cv + (size_t)row * CC;
    float v[4];
    float mx = -1e30f;
    #pragma unroll
    for (int q = 0; q < 4; q++) {
        int j = t + q * 256;
        v[q] = (j < CC) ? src[j] : -1e30f;
        mx = fmaxf(mx, v[q]);
    }
    mx = blockMax256(mx);
    float sum = 0.f;
    #pragma unroll
    for (int q = 0; q < 4; q++) {
        int j = t + q * 256;
        float e = (j < CC) ? fast_expf(v[q] - mx) : 0.f;
        v[q] = e;
        sum += e;
    }
    sum = blockSum256(sum);
    float inv = 1.0f / sum;
    #pragma unroll
    for (int q = 0; q < 4; q++) {
        int j = t + q * 256;
        if (j < CC) dst[j] = v[q] * inv;
    }
}

// ============================================================================
// Kernel 3: transpose g_cv rows [NL,NT) fp32 -> g_cvT[c][k] fp16 (k >= NL)
// ============================================================================
__global__ void transpose_cv_kernel() {
    __shared__ float s[32][33];
    const int k0 = NL + blockIdx.x * 32, c0 = blockIdx.y * 32;
    const int tx = threadIdx.x & 31, ty = threadIdx.x >> 5;
    #pragma unroll
    for (int q = 0; q < 4; q++) {
        int k = k0 + ty + q * 8, c = c0 + tx;
        s[ty + q * 8][tx] = (c < CC) ? g_cv[(size_t)k * CC + c] : 0.f;
    }
    __syncthreads();
    #pragma unroll
    for (int q = 0; q < 4; q++) {
        int c = c0 + ty + q * 8, k = k0 + tx;
        g_cvT[(size_t)c * NT + k] = __float2half_rn(s[tx][ty + q * 8]);
    }
}

// ============================================================================
// Kernel 4: GEMM1 (HMMA): dot = n@n^T via fp16 hi/lo 3-pass; E = exp(10*dot)
// SYMMETRIC: only upper-triangular 128x128 blocks (bi <= bj); off-diagonal
// blocks also write the transposed tile (staged through SMEM).
// Fused rowsums -> g_rsum via warp-reduced atomics.
// 3-stage cp.async pipeline; stage = Ah|Al|Bh|Bl 16KB each = 64KB; 3 = 192KB.
// ============================================================================
__device__ __forceinline__ void g1_load(uint32_t sb, int s, int c, int i0, int j0, int t) {
    #pragma unroll
    for (int q = 0; q < 4; q++) {
        int u = t + q * 256, row = u >> 3, seg = u & 7;
        uint32_t so = smoff(row, seg);
        uint32_t dA = sb + s * 65536 + so;
        size_t ga = ((size_t)(i0 + row) * D + c * 64 + seg * 8) * 2;
        size_t gb = ((size_t)(j0 + row) * D + c * 64 + seg * 8) * 2;
        CP16(dA,         (const char*)g_nh + ga);
        CP16(dA + 16384, (const char*)g_nl + ga);
        CP16(dA + 32768, (const char*)g_nh + gb);
        CP16(dA + 49152, (const char*)g_nl + gb);
    }
}

static constexpr int NB = NT / 128;  // 64 blocks per dim
static constexpr int TP = 136;       // transpose-stage pitch in halves

__global__ __launch_bounds__(256) void gemm1_kernel() {
    extern __shared__ char smem[];
    const uint32_t sb = smem_u32(smem);
    const int t = threadIdx.x, lane = t & 31, w = t >> 5;
    const int wm = w >> 2, wn = w & 3;

    // triangular decode: blockIdx.x -> (bi, bj), bi <= bj
    int bi = 0, rem = blockIdx.x;
    while (rem >= NB - bi) { rem -= NB - bi; bi++; }
    const int bj = bi + rem;
    const int i0 = bi * 128, j0 = bj * 128;

    float acc[4][4][4];
    #pragma unroll
    for (int a = 0; a < 4; a++)
        #pragma unroll
        for (int b = 0; b < 4; b++)
            #pragma unroll
            for (int cth = 0; cth < 4; cth++) acc[a][b][cth] = 0.f;

    const int rA = wm * 64 + (lane & 15);
    const int sA = lane >> 4;
    const int rB = wn * 32 + ((lane >> 4) & 1) * 8 + (lane & 7);
    const int sB = (lane >> 3) & 1;

    g1_load(sb, 0, 0, i0, j0, t); CP_COMMIT();
    g1_load(sb, 1, 1, i0, j0, t); CP_COMMIT();

    for (int c = 0; c < 8; c++) {
        const int st = c % 3;
        if (c + 2 < 8) g1_load(sb, (c + 2) % 3, c + 2, i0, j0, t);
        CP_COMMIT();   // always commit (possibly empty group) -> WAIT2 retires chunk c
        CP_WAIT2();
        __syncthreads();
        const uint32_t bAh = sb + st * 65536;
        const uint32_t bAl = bAh + 16384, bBh = bAh + 32768, bBl = bAh + 49152;
        #pragma unroll
        for (int kk = 0; kk < 4; kk++) {
            uint32_t ah[4][4], al[4][4], bh[8], bl[8];
            #pragma unroll
            for (int mt = 0; mt < 4; mt++)
                ldm_x4(ah[mt], bAh + smoff(rA + mt * 16, 2 * kk + sA));
            #pragma unroll
            for (int jj = 0; jj < 2; jj++)
                ldm_x4(bh + jj * 4, bBh + smoff(rB + jj * 16, 2 * kk + sB));
            #pragma unroll
            for (int mt = 0; mt < 4; mt++)
                #pragma unroll
                for (int nt = 0; nt < 4; nt++)
                    mma16816(acc[mt][nt], ah[mt], bh + nt * 2);
            #pragma unroll
            for (int jj = 0; jj < 2; jj++)
                ldm_x4(bl + jj * 4, bBl + smoff(rB + jj * 16, 2 * kk + sB));
            #pragma unroll
            for (int mt = 0; mt < 4; mt++)
                #pragma unroll
                for (int nt = 0; nt < 4; nt++)
                    mma16816(acc[mt][nt], ah[mt], bl + nt * 2);
            #pragma unroll
            for (int mt = 0; mt < 4; mt++)
                ldm_x4(al[mt], bAl + smoff(rA + mt * 16, 2 * kk + sA));
            #pragma unroll
            for (int mt = 0; mt < 4; mt++)
                #pragma unroll
                for (int nt = 0; nt < 4; nt++)
                    mma16816(acc[mt][nt], al[mt], bh + nt * 2);
        }
        __syncthreads();
    }
    // All stage-buffer reads done; smem reusable for transpose staging.

    // Epilogue: E = exp(10*acc) -> fp16; fused row sums.
    const int g = lane >> 2, cq = lane & 3;
    __half* sT = (__half*)smem;  // pitch TP halves
    #pragma unroll
    for (int mt = 0; mt < 4; mt++) {
        #pragma unroll
        for (int h = 0; h < 2; h++) {
            const int rl = wm * 64 + mt * 16 + g + h * 8;      // local row
            __half* erow = g_E + (size_t)(i0 + rl) * NT + j0 + wn * 32;
            float rs = 0.f;
            #pragma unroll
            for (int nt = 0; nt < 4; nt++) {
                float e0 = fast_expf(acc[mt][nt][2 * h] * 10.f);
                float e1 = fast_expf(acc[mt][nt][2 * h + 1] * 10.f);
                __half2 p = __floats2half2_rn(e0, e1);
                *(__half2*)(erow + nt * 8 + cq * 2) = p;
                float2 pf = __half22float2(p);   // sum the rounded values
                rs += pf.x + pf.y;
                if (bi != bj) {
                    const int cl = wn * 32 + nt * 8 + cq * 2;
                    sT[(size_t)cl * TP + rl]       = __low2half(p);
                    sT[(size_t)(cl + 1) * TP + rl] = __high2half(p);
                }
            }
            // reduce across the 4 cq lanes sharing this row
            rs += __shfl_xor_sync(0xffffffffu, rs, 1);
            rs += __shfl_xor_sync(0xffffffffu, rs, 2);
            if (cq == 0) atomicAdd(&g_rsum[i0 + rl], rs);
        }
    }
    if (bi != bj) {
        __syncthreads();
        // coalesced write of transposed tile + its row sums (= column sums)
        #pragma unroll
        for (int q = 0; q < 8; q++) {
            int u = t + q * 256;
            int row = u >> 4, seg = u & 15;  // seg == lane & 15
            uint4 v = *(const uint4*)(sT + row * TP + seg * 8);
            *(uint4*)(g_E + (size_t)(j0 + row) * NT + i0 + seg * 8) = v;
            const __half2* hh = (const __half2*)&v;
            float s = 0.f;
            #pragma unroll
            for (int k = 0; k < 4; k++) {
                float2 f = __half22float2(hh[k]);
                s += f.x + f.y;
            }
            s += __shfl_xor_sync(0xffffffffu, s, 1);
            s += __shfl_xor_sync(0xffffffffu, s, 2);
            s += __shfl_xor_sync(0xffffffffu, s, 4);
            s += __shfl_xor_sync(0xffffffffu, s, 8);
            if (seg == 0) atomicAdd(&g_rsum[j0 + row], s);
        }
    }
}

// ============================================================================
// Kernel 5: GEMM2 (HMMA): out = (E[:,2048:] @ cvT[:,2048:]^T) / rsum
// K = 6144 (96 chunks of 64). 3-stage pipeline, stage 32KB (A|B), 2 CTAs/SM.
// ============================================================================
__device__ __forceinline__ void g2_load(uint32_t sb, int s, int c, int i0, int j0, int t) {
    #pragma unroll
    for (int q = 0; q < 4; q++) {
        int u = t + q * 256, row = u >> 3, seg = u & 7;
        uint32_t so = smoff(row, seg);
        uint32_t dA = sb + s * 32768 + so;
        size_t ga = ((size_t)(i0 + row) * NT + NL + c * 64 + seg * 8) * 2;
        size_t gb = ((size_t)(j0 + row) * NT + NL + c * 64 + seg * 8) * 2;
        CP16(dA,         (const char*)g_E + ga);
        CP16(dA + 16384, (const char*)g_cvT + gb);
    }
}

__global__ __launch_bounds__(256, 2) void gemm2_kernel(float* __restrict__ out) {
    extern __shared__ char smem[];
    const uint32_t sb = smem_u32(smem);
    const int t = threadIdx.x, lane = t & 31, w = t >> 5;
    const int wm = w >> 2, wn = w & 3;
    const int i0 = blockIdx.y * 128, j0 = blockIdx.x * 128;

    float acc[4][4][4];
    #pragma unroll
    for (int a = 0; a < 4; a++)
        #pragma unroll
        for (int b = 0; b < 4; b++)
            #pragma unroll
            for (int cth = 0; cth < 4; cth++) acc[a][b][cth] = 0.f;

    const int rA = wm * 64 + (lane & 15);
    const int sA = lane >> 4;
    const int rB = wn * 32 + ((lane >> 4) & 1) * 8 + (lane & 7);
    const int sB = (lane >> 3) & 1;

    g2_load(sb, 0, 0, i0, j0, t); CP_COMMIT();
    g2_load(sb, 1, 1, i0, j0, t); CP_COMMIT();

    constexpr int NCH = (NT - NL) / 64;  // 96
    for (int c = 0; c < NCH; c++) {
        const int st = c % 3;
        if (c + 2 < NCH) g2_load(sb, (c + 2) % 3, c + 2, i0, j0, t);
        CP_COMMIT();
        CP_WAIT2();
        __syncthreads();
        const uint32_t bA = sb + st * 32768;
        const uint32_t bB = bA + 16384;
        #pragma unroll
        for (int kk = 0; kk < 4; kk++) {
            uint32_t af[4][4], bf[8];
            #pragma unroll
            for (int mt = 0; mt < 4; mt++)
                ldm_x4(af[mt], bA + smoff(rA + mt * 16, 2 * kk + sA));
            #pragma unroll
            for (int jj = 0; jj < 2; jj++)
                ldm_x4(bf + jj * 4, bB + smoff(rB + jj * 16, 2 * kk + sB));
            #pragma unroll
            for (int mt = 0; mt < 4; mt++)
                #pragma unroll
                for (int nt = 0; nt < 4; nt++)
                    mma16816(acc[mt][nt], af[mt], bf + nt * 2);
        }
        __syncthreads();
    }

    const int g = lane >> 2, cq = lane & 3;
    #pragma unroll
    for (int mt = 0; mt < 4; mt++) {
        #pragma unroll
        for (int h = 0; h < 2; h++) {
            const int row = i0 + wm * 64 + mt * 16 + g + h * 8;
            const float inv = 1.0f / g_rsum[row];
            float* crow = out + (size_t)row * CC;
            #pragma unroll
            for (int nt = 0; nt < 4; nt++) {
                int col = j0 + wn * 32 + nt * 8 + cq * 2;
                if (col < CC) {
                    float2 v = make_float2(acc[mt][nt][2 * h] * inv,
                                           acc[mt][nt][2 * h + 1] * inv);
                    *(float2*)(crow + col) = v;
                }
            }
        }
    }
}

// ============================================================================
// Kernel 6: scatter the labeled (one-hot) K-range into out.
// out[i][c] += (sum_{j<NL, label[j]==c} E[i][j]) / rsum[i]
// ============================================================================
__global__ __launch_bounds__(256) void scatter_kernel(float* __restrict__ out) {
    __shared__ float accum[CC];
    __shared__ int lab[NL];
    const int i = blockIdx.x, t = threadIdx.x;
    #pragma unroll
    for (int q = 0; q < 4; q++) {
        int c = t + q * 256;
        if (c < CC) accum[c] = 0.f;
    }
    #pragma unroll
    for (int q = 0; q < 8; q++) lab[t + q * 256] = g_label[t + q * 256];
    __syncthreads();
    uint4 u = ((const uint4*)(g_E + (size_t)i * NT))[t];
    const __half2* h = (const __half2*)&u;
    const int j0 = t * 8;
    #pragma unroll
    for (int k = 0; k < 4; k++) {
        float2 f = __half22float2(h[k]);
        atomicAdd(&accum[lab[j0 + 2 * k]],     f.x);
        atomicAdd(&accum[lab[j0 + 2 * k + 1]], f.y);
    }
    __syncthreads();
    const float inv = 1.0f / g_rsum[i];
    float* crow = out + (size_t)i * CC;
    #pragma unroll
    for (int q = 0; q < 4; q++) {
        int c = t + q * 256;
        if (c < CC) crow[c] += accum[c] * inv;
    }
}

// ============================================================================
// Launch. Output layout (float32):
//   [0)         anchor_feat    3145728
//   [3145728)   positive_feat  3145728
//   [6291456)   lb_feat        1048576
//   [7340032)   lb_one_hot     2048000
//   [9388032)   new_lb||new_ulb1  8192000 (contiguous 8192x1000)
//   [17580032)  logits_x_ulb_2 6144000
// ============================================================================
extern "C" void kernel_launch(void* const* d_in, const int* in_sizes, int n_in,
                              void* d_out, int out_size) {
    const float* anchor   = (const float*)d_in[0];
    const float* positive = (const float*)d_in[1];
    const float* lb_feat  = (const float*)d_in[2];
    const float* lb_oh    = (const float*)d_in[3];
    const float* lg_ulb1  = (const float*)d_in[5];
    const float* lg_ulb2  = (const float*)d_in[6];
    float* out = (float*)d_out;

    cudaMemcpyAsync(out,            anchor,   (size_t)NU * D  * sizeof(float), cudaMemcpyDeviceToDevice, 0);
    cudaMemcpyAsync(out + 3145728,  positive, (size_t)NU * D  * sizeof(float), cudaMemcpyDeviceToDevice, 0);
    cudaMemcpyAsync(out + 6291456,  lb_feat,  (size_t)NL * D  * sizeof(float), cudaMemcpyDeviceToDevice, 0);
    cudaMemcpyAsync(out + 7340032,  lb_oh,    (size_t)NL * CC * sizeof(float), cudaMemcpyDeviceToDevice, 0);
    cudaMemcpyAsync(out + 17580032, lg_ulb2,  (size_t)NU * CC * sizeof(float), cudaMemcpyDeviceToDevice, 0);

    void* rsum_ptr = nullptr;
    cudaGetSymbolAddress(&rsum_ptr, g_rsum);
    cudaMemsetAsync(rsum_ptr, 0, NT * sizeof(float), 0);

    normalize_kernel<<<NT, 128>>>(lb_feat, anchor);
    classval_kernel<<<NT, 256>>>(lb_oh, lg_ulb1);
    transpose_cv_kernel<<<dim3((NT - NL) / 32, 1024 / 32), 256>>>();

    cudaFuncSetAttribute(gemm1_kernel, cudaFuncAttributeMaxDynamicSharedMemorySize, 196608);
    cudaFuncSetAttribute(gemm2_kernel, cudaFuncAttributeMaxDynamicSharedMemorySize, 98304);

    gemm1_kernel<<<NB * (NB + 1) / 2, 256, 196608>>>();   // 2080 triangular blocks
    gemm2_kernel<<<dim3(8, 64), 256, 98304>>>(out + 9388032);
    scatter_kernel<<<NT, 256>>>(out + 9388032);
}

// round 6
// speedup vs baseline: 8.7616x; 1.0029x over previous
#include <cuda_runtime.h>
#include <cuda_fp16.h>
#include <cstdint>

// Problem sizes
static constexpr int NL = 2048;
static constexpr int NU = 6144;
static constexpr int NT = 8192;   // NL + NU
static constexpr int D  = 512;
static constexpr int CC = 1000;

// Scratch (device globals; no allocation allowed)
__device__ __half g_nh[(size_t)NT * D];      // normalized feats hi fp16 (8MB)
__device__ __half g_nl[(size_t)NT * D];      // normalized feats lo fp16 (8MB)
__device__ float  g_cv[(size_t)NT * CC];     // class_val fp32 (rows >= NL used)
__device__ __half g_cvT[(size_t)1024 * NT];  // class_val^T fp16 (cols >= NL used)
__device__ __half g_E[(size_t)NT * NT];      // exp(S) fp16 (134MB)
__device__ float  g_rsum[NT];                // softmax denominators (atomic-accumulated)
__device__ int    g_label[NL];               // argmax of lb_one_hot rows

// ============================================================================
// Helpers
// ============================================================================
__device__ __forceinline__ uint32_t smem_u32(const void* p) {
    uint32_t a;
    asm("{ .reg .u64 t; cvta.to.shared.u64 t, %1; cvt.u32.u64 %0, t; }" : "=r"(a) : "l"(p));
    return a;
}
// swizzled byte offset inside a tile of 128B rows (8 x 16B segments per row)
__device__ __forceinline__ uint32_t smoff(int row, int seg) {
    return (uint32_t)(row * 128 + ((seg ^ (row & 7)) << 4));
}
// swizzled byte offset inside a tile of 64B rows (4 x 16B segments per row)
__device__ __forceinline__ uint32_t smoff32(int row, int seg) {
    return (uint32_t)(row * 64 + ((seg ^ (row & 3)) << 4));
}
#define CP16(dst, src) \
    asm volatile("cp.async.cg.shared.global [%0], [%1], 16;" :: "r"(dst), "l"(src) : "memory")
#define CP_COMMIT() asm volatile("cp.async.commit_group;" ::: "memory")
#define CP_WAIT2() asm volatile("cp.async.wait_group 2;" ::: "memory")

__device__ __forceinline__ void ldm_x4(uint32_t* r, uint32_t addr) {
    asm volatile("ldmatrix.sync.aligned.m8n8.x4.shared.b16 {%0,%1,%2,%3}, [%4];"
                 : "=r"(r[0]), "=r"(r[1]), "=r"(r[2]), "=r"(r[3]) : "r"(addr));
}
__device__ __forceinline__ void mma16816(float* d, const uint32_t* a, const uint32_t* b) {
    asm volatile(
        "mma.sync.aligned.m16n8k16.row.col.f32.f16.f16.f32 "
        "{%0,%1,%2,%3}, {%4,%5,%6,%7}, {%8,%9}, {%0,%1,%2,%3};"
        : "+f"(d[0]), "+f"(d[1]), "+f"(d[2]), "+f"(d[3])
        : "r"(a[0]), "r"(a[1]), "r"(a[2]), "r"(a[3]), "r"(b[0]), "r"(b[1]));
}

// FMA-only exp, valid for |x| <= ~11, rel err < 2e-7
__device__ __forceinline__ float fast_expf(float x) {
    float z = x * 1.4426950408889634f;
    float n = rintf(z);
    float r = fmaf(n, -0.6931471824645996f, x);
    r = fmaf(n, 1.9046542743e-9f, r);
    float p = 1.3888889225e-3f;
    p = fmaf(p, r, 8.3333337680e-3f);
    p = fmaf(p, r, 4.1666667908e-2f);
    p = fmaf(p, r, 1.6666667163e-1f);
    p = fmaf(p, r, 5.0e-1f);
    p = fmaf(p, r, 1.0f);
    p = fmaf(p, r, 1.0f);
    float s = __int_as_float(((int)n + 127) << 23);
    return p * s;
}

__device__ __forceinline__ float blockMax256(float v) {
    __shared__ float s[8];
    #pragma unroll
    for (int o = 16; o > 0; o >>= 1) v = fmaxf(v, __shfl_xor_sync(0xffffffffu, v, o));
    if ((threadIdx.x & 31) == 0) s[threadIdx.x >> 5] = v;
    __syncthreads();
    float r = s[0];
    #pragma unroll
    for (int i = 1; i < 8; i++) r = fmaxf(r, s[i]);
    __syncthreads();
    return r;
}
__device__ __forceinline__ float blockSum256(float v) {
    __shared__ float s[8];
    #pragma unroll
    for (int o = 16; o > 0; o >>= 1) v += __shfl_xor_sync(0xffffffffu, v, o);
    if ((threadIdx.x & 31) == 0) s[threadIdx.x >> 5] = v;
    __syncthreads();
    float r = s[0];
    #pragma unroll
    for (int i = 1; i < 8; i++) r += s[i];
    __syncthreads();
    return r;
}

// ============================================================================
// Kernel 1: L2-normalize concat(lb_feat, anchor) -> fp16 hi/lo split
// ============================================================================
__global__ void normalize_kernel(const float* __restrict__ lb_feat,
                                 const float* __restrict__ anchor) {
    const int row = blockIdx.x;
    const int t = threadIdx.x;
    const float* src = (row < NL) ? lb_feat + (size_t)row * D
                                  : anchor + (size_t)(row - NL) * D;
    float4 v = ((const float4*)src)[t];
    float ss = v.x * v.x + v.y * v.y + v.z * v.z + v.w * v.w;
    #pragma unroll
    for (int o = 16; o > 0; o >>= 1) ss += __shfl_xor_sync(0xffffffffu, ss, o);
    __shared__ float ws[4];
    if ((t & 31) == 0) ws[t >> 5] = ss;
    __syncthreads();
    float tot = ws[0] + ws[1] + ws[2] + ws[3];
    float sc = 1.0f / fmaxf(sqrtf(tot), 1e-12f);
    float n0 = v.x * sc, n1 = v.y * sc, n2 = v.z * sc, n3 = v.w * sc;
    __half h0 = __float2half_rn(n0), h1 = __float2half_rn(n1);
    __half h2 = __float2half_rn(n2), h3 = __float2half_rn(n3);
    __half l0 = __float2half_rn(n0 - __half2float(h0));
    __half l1 = __float2half_rn(n1 - __half2float(h1));
    __half l2 = __float2half_rn(n2 - __half2float(h2));
    __half l3 = __float2half_rn(n3 - __half2float(h3));
    __half2 hA = __halves2half2(h0, h1), hB = __halves2half2(h2, h3);
    __half2 lA = __halves2half2(l0, l1), lB = __halves2half2(l2, l3);
    uint2 hp, lp;
    hp.x = *(uint32_t*)&hA; hp.y = *(uint32_t*)&hB;
    lp.x = *(uint32_t*)&lA; lp.y = *(uint32_t*)&lB;
    ((uint2*)(g_nh + (size_t)row * D))[t] = hp;
    ((uint2*)(g_nl + (size_t)row * D))[t] = lp;
}

// ============================================================================
// Kernel 2: rows < NL: extract label (argmax of one-hot).
//           rows >= NL: softmax(logits_x_ulb_1) -> g_cv.
// ============================================================================
__global__ void classval_kernel(const float* __restrict__ lb_one_hot,
                                const float* __restrict__ logits) {
    const int row = blockIdx.x;
    const int t = threadIdx.x;
    if (row < NL) {
        const float* src = lb_one_hot + (size_t)row * CC;
        #pragma unroll
        for (int q = 0; q < 4; q++) {
            int c = t + q * 256;
            if (c < CC && src[c] > 0.5f) g_label[row] = c;
        }
        return;
    }
    const float* src = logits + (size_t)(row - NL) * CC;
    float* dst = g_cv + (size_t)row * CC;
    float v[4];
    float mx = -1e30f;
    #pragma unroll
    for (int q = 0; q < 4; q++) {
        int j = t + q * 256;
        v[q] = (j < CC) ? src[j] : -1e30f;
        mx = fmaxf(mx, v[q]);
    }
    mx = blockMax256(mx);
    float sum = 0.f;
    #pragma unroll
    for (int q = 0; q < 4; q++) {
        int j = t + q * 256;
        float e = (j < CC) ? fast_expf(v[q] - mx) : 0.f;
        v[q] = e;
        sum += e;
    }
    sum = blockSum256(sum);
    float inv = 1.0f / sum;
    #pragma unroll
    for (int q = 0; q < 4; q++) {
        int j = t + q * 256;
        if (j < CC) dst[j] = v[q] * inv;
    }
}

// ============================================================================
// Kernel 3: transpose g_cv rows [NL,NT) fp32 -> g_cvT[c][k] fp16 (k >= NL)
// ============================================================================
__global__ void transpose_cv_kernel() {
    __shared__ float s[32][33];
    const int k0 = NL + blockIdx.x * 32, c0 = blockIdx.y * 32;
    const int tx = threadIdx.x & 31, ty = threadIdx.x >> 5;
    #pragma unroll
    for (int q = 0; q < 4; q++) {
        int k = k0 + ty + q * 8, c = c0 + tx;
        s[ty + q * 8][tx] = (c < CC) ? g_cv[(size_t)k * CC + c] : 0.f;
    }
    __syncthreads();
    #pragma unroll
    for (int q = 0; q < 4; q++) {
        int c = c0 + ty + q * 8, k = k0 + tx;
        g_cvT[(size_t)c * NT + k] = __float2half_rn(s[tx][ty + q * 8]);
    }
}

// ============================================================================
// Kernel 4: GEMM1 (HMMA): dot = n@n^T via fp16 hi/lo 3-pass; E = exp(10*dot)
// SYMMETRIC: only upper-triangular 128x128 blocks (bi <= bj); off-diagonal
// blocks also write the transposed tile (staged through SMEM).
// Fused rowsums -> g_rsum via warp-reduced atomics.
// kc=32, 3-stage cp.async; stage = Ah|Al|Bh|Bl 8KB each = 32KB; 3 = 96KB.
// 2 CTAs/SM (the R5 lesson: 1 CTA/SM left the tensor pipe at 57%).
// ============================================================================
__device__ __forceinline__ void g1_load(uint32_t sb, int s, int c, int i0, int j0, int t) {
    #pragma unroll
    for (int q = 0; q < 2; q++) {
        int u = t + q * 256, row = u >> 2, seg = u & 3;
        uint32_t so = smoff32(row, seg);
        uint32_t dA = sb + s * 32768 + so;
        size_t ga = ((size_t)(i0 + row) * D + c * 32 + seg * 8) * 2;
        size_t gb = ((size_t)(j0 + row) * D + c * 32 + seg * 8) * 2;
        CP16(dA,         (const char*)g_nh + ga);
        CP16(dA + 8192,  (const char*)g_nl + ga);
        CP16(dA + 16384, (const char*)g_nh + gb);
        CP16(dA + 24576, (const char*)g_nl + gb);
    }
}

static constexpr int NB = NT / 128;  // 64 blocks per dim
static constexpr int TP = 136;       // transpose-stage pitch in halves

__global__ __launch_bounds__(256, 2) void gemm1_kernel() {
    extern __shared__ char smem[];
    const uint32_t sb = smem_u32(smem);
    const int t = threadIdx.x, lane = t & 31, w = t >> 5;
    const int wm = w >> 2, wn = w & 3;

    // triangular decode: blockIdx.x -> (bi, bj), bi <= bj
    int bi = 0, rem = blockIdx.x;
    while (rem >= NB - bi) { rem -= NB - bi; bi++; }
    const int bj = bi + rem;
    const int i0 = bi * 128, j0 = bj * 128;

    float acc[4][4][4];
    #pragma unroll
    for (int a = 0; a < 4; a++)
        #pragma unroll
        for (int b = 0; b < 4; b++)
            #pragma unroll
            for (int cth = 0; cth < 4; cth++) acc[a][b][cth] = 0.f;

    const int rA = wm * 64 + (lane & 15);
    const int sA = lane >> 4;                              // 0..1
    const int rB = wn * 32 + ((lane >> 4) & 1) * 8 + (lane & 7);
    const int sB = (lane >> 3) & 1;                        // 0..1

    g1_load(sb, 0, 0, i0, j0, t); CP_COMMIT();
    g1_load(sb, 1, 1, i0, j0, t); CP_COMMIT();

    constexpr int NCH = D / 32;  // 16 chunks
    for (int c = 0; c < NCH; c++) {
        const int st = c % 3;
        if (c + 2 < NCH) g1_load(sb, (c + 2) % 3, c + 2, i0, j0, t);
        CP_COMMIT();   // always commit -> WAIT2 retires chunk c
        CP_WAIT2();
        __syncthreads();
        const uint32_t bAh = sb + st * 32768;
        const uint32_t bAl = bAh + 8192, bBh = bAh + 16384, bBl = bAh + 24576;
        #pragma unroll
        for (int kk = 0; kk < 2; kk++) {
            uint32_t ah[4][4], al[4][4], bh[8], bl[8];
            #pragma unroll
            for (int mt = 0; mt < 4; mt++)
                ldm_x4(ah[mt], bAh + smoff32(rA + mt * 16, 2 * kk + sA));
            #pragma unroll
            for (int jj = 0; jj < 2; jj++)
                ldm_x4(bh + jj * 4, bBh + smoff32(rB + jj * 16, 2 * kk + sB));
            #pragma unroll
            for (int mt = 0; mt < 4; mt++)
                #pragma unroll
                for (int nt = 0; nt < 4; nt++)
                    mma16816(acc[mt][nt], ah[mt], bh + nt * 2);
            #pragma unroll
            for (int jj = 0; jj < 2; jj++)
                ldm_x4(bl + jj * 4, bBl + smoff32(rB + jj * 16, 2 * kk + sB));
            #pragma unroll
            for (int mt = 0; mt < 4; mt++)
                #pragma unroll
                for (int nt = 0; nt < 4; nt++)
                    mma16816(acc[mt][nt], ah[mt], bl + nt * 2);
            #pragma unroll
            for (int mt = 0; mt < 4; mt++)
                ldm_x4(al[mt], bAl + smoff32(rA + mt * 16, 2 * kk + sA));
            #pragma unroll
            for (int mt = 0; mt < 4; mt++)
                #pragma unroll
                for (int nt = 0; nt < 4; nt++)
                    mma16816(acc[mt][nt], al[mt], bh + nt * 2);
        }
        __syncthreads();
    }
    // All stage-buffer reads done; smem reusable for transpose staging.

    // Epilogue: E = exp(10*acc) -> fp16; fused row sums.
    const int g = lane >> 2, cq = lane & 3;
    __half* sT = (__half*)smem;  // pitch TP halves
    #pragma unroll
    for (int mt = 0; mt < 4; mt++) {
        #pragma unroll
        for (int h = 0; h < 2; h++) {
            const int rl = wm * 64 + mt * 16 + g + h * 8;      // local row
            __half* erow = g_E + (size_t)(i0 + rl) * NT + j0 + wn * 32;
            float rs = 0.f;
            #pragma unroll
            for (int nt = 0; nt < 4; nt++) {
                float e0 = fast_expf(acc[mt][nt][2 * h] * 10.f);
                float e1 = fast_expf(acc[mt][nt][2 * h + 1] * 10.f);
                __half2 p = __floats2half2_rn(e0, e1);
                *(__half2*)(erow + nt * 8 + cq * 2) = p;
                float2 pf = __half22float2(p);   // sum the rounded values
                rs += pf.x + pf.y;
                if (bi != bj) {
                    const int cl = wn * 32 + nt * 8 + cq * 2;
                    sT[(size_t)cl * TP + rl]       = __low2half(p);
                    sT[(size_t)(cl + 1) * TP + rl] = __high2half(p);
                }
            }
            // reduce across the 4 cq lanes sharing this row
            rs += __shfl_xor_sync(0xffffffffu, rs, 1);
            rs += __shfl_xor_sync(0xffffffffu, rs, 2);
            if (cq == 0) atomicAdd(&g_rsum[i0 + rl], rs);
        }
    }
    if (bi != bj) {
        __syncthreads();
        // coalesced write of transposed tile + its row sums (= column sums)
        #pragma unroll
        for (int q = 0; q < 8; q++) {
            int u = t + q * 256;
            int row = u >> 4, seg = u & 15;  // seg == lane & 15
            uint4 v = *(const uint4*)(sT + row * TP + seg * 8);
            *(uint4*)(g_E + (size_t)(j0 + row) * NT + i0 + seg * 8) = v;
            const __half2* hh = (const __half2*)&v;
            float s = 0.f;
            #pragma unroll
            for (int k = 0; k < 4; k++) {
                float2 f = __half22float2(hh[k]);
                s += f.x + f.y;
            }
            s += __shfl_xor_sync(0xffffffffu, s, 1);
            s += __shfl_xor_sync(0xffffffffu, s, 2);
            s += __shfl_xor_sync(0xffffffffu, s, 4);
            s += __shfl_xor_sync(0xffffffffu, s, 8);
            if (seg == 0) atomicAdd(&g_rsum[j0 + row], s);
        }
    }
}

// ============================================================================
// Kernel 5: GEMM2 (HMMA): out = (E[:,2048:] @ cvT[:,2048:]^T) / rsum
// K = 6144 (96 chunks of 64). 3-stage pipeline, stage 32KB (A|B), 2 CTAs/SM.
// ============================================================================
__device__ __forceinline__ void g2_load(uint32_t sb, int s, int c, int i0, int j0, int t) {
    #pragma unroll
    for (int q = 0; q < 4; q++) {
        int u = t + q * 256, row = u >> 3, seg = u & 7;
        uint32_t so = smoff(row, seg);
        uint32_t dA = sb + s * 32768 + so;
        size_t ga = ((size_t)(i0 + row) * NT + NL + c * 64 + seg * 8) * 2;
        size_t gb = ((size_t)(j0 + row) * NT + NL + c * 64 + seg * 8) * 2;
        CP16(dA,         (const char*)g_E + ga);
        CP16(dA + 16384, (const char*)g_cvT + gb);
    }
}

__global__ __launch_bounds__(256, 2) void gemm2_kernel(float* __restrict__ out) {
    extern __shared__ char smem[];
    const uint32_t sb = smem_u32(smem);
    const int t = threadIdx.x, lane = t & 31, w = t >> 5;
    const int wm = w >> 2, wn = w & 3;
    const int i0 = blockIdx.y * 128, j0 = blockIdx.x * 128;

    float acc[4][4][4];
    #pragma unroll
    for (int a = 0; a < 4; a++)
        #pragma unroll
        for (int b = 0; b < 4; b++)
            #pragma unroll
            for (int cth = 0; cth < 4; cth++) acc[a][b][cth] = 0.f;

    const int rA = wm * 64 + (lane & 15);
    const int sA = lane >> 4;
    const int rB = wn * 32 + ((lane >> 4) & 1) * 8 + (lane & 7);
    const int sB = (lane >> 3) & 1;

    g2_load(sb, 0, 0, i0, j0, t); CP_COMMIT();
    g2_load(sb, 1, 1, i0, j0, t); CP_COMMIT();

    constexpr int NCH = (NT - NL) / 64;  // 96
    for (int c = 0; c < NCH; c++) {
        const int st = c % 3;
        if (c + 2 < NCH) g2_load(sb, (c + 2) % 3, c + 2, i0, j0, t);
        CP_COMMIT();
        CP_WAIT2();
        __syncthreads();
        const uint32_t bA = sb + st * 32768;
        const uint32_t bB = bA + 16384;
        #pragma unroll
        for (int kk = 0; kk < 4; kk++) {
            uint32_t af[4][4], bf[8];
            #pragma unroll
            for (int mt = 0; mt < 4; mt++)
                ldm_x4(af[mt], bA + smoff(rA + mt * 16, 2 * kk + sA));
            #pragma unroll
            for (int jj = 0; jj < 2; jj++)
                ldm_x4(bf + jj * 4, bB + smoff(rB + jj * 16, 2 * kk + sB));
            #pragma unroll
            for (int mt = 0; mt < 4; mt++)
                #pragma unroll
                for (int nt = 0; nt < 4; nt++)
                    mma16816(acc[mt][nt], af[mt], bf + nt * 2);
        }
        __syncthreads();
    }

    const int g = lane >> 2, cq = lane & 3;
    #pragma unroll
    for (int mt = 0; mt < 4; mt++) {
        #pragma unroll
        for (int h = 0; h < 2; h++) {
            const int row = i0 + wm * 64 + mt * 16 + g + h * 8;
            const float inv = 1.0f / g_rsum[row];
            float* crow = out + (size_t)row * CC;
            #pragma unroll
            for (int nt = 0; nt < 4; nt++) {
                int col = j0 + wn * 32 + nt * 8 + cq * 2;
                if (col < CC) {
                    float2 v = make_float2(acc[mt][nt][2 * h] * inv,
                                           acc[mt][nt][2 * h + 1] * inv);
                    *(float2*)(crow + col) = v;
                }
            }
        }
    }
}

// ============================================================================
// Kernel 6: scatter the labeled (one-hot) K-range into out.
// out[i][c] += (sum_{j<NL, label[j]==c} E[i][j]) / rsum[i]
// ============================================================================
__global__ __launch_bounds__(256) void scatter_kernel(float* __restrict__ out) {
    __shared__ float accum[CC];
    __shared__ int lab[NL];
    const int i = blockIdx.x, t = threadIdx.x;
    #pragma unroll
    for (int q = 0; q < 4; q++) {
        int c = t + q * 256;
        if (c < CC) accum[c] = 0.f;
    }
    #pragma unroll
    for (int q = 0; q < 8; q++) lab[t + q * 256] = g_label[t + q * 256];
    __syncthreads();
    uint4 u = ((const uint4*)(g_E + (size_t)i * NT))[t];
    const __half2* h = (const __half2*)&u;
    const int j0 = t * 8;
    #pragma unroll
    for (int k = 0; k < 4; k++) {
        float2 f = __half22float2(h[k]);
        atomicAdd(&accum[lab[j0 + 2 * k]],     f.x);
        atomicAdd(&accum[lab[j0 + 2 * k + 1]], f.y);
    }
    __syncthreads();
    const float inv = 1.0f / g_rsum[i];
    float* crow = out + (size_t)i * CC;
    #pragma unroll
    for (int q = 0; q < 4; q++) {
        int c = t + q * 256;
        if (c < CC) crow[c] += accum[c] * inv;
    }
}

// ============================================================================
// Launch. Output layout (float32):
//   [0)         anchor_feat    3145728
//   [3145728)   positive_feat  3145728
//   [6291456)   lb_feat        1048576
//   [7340032)   lb_one_hot     2048000
//   [9388032)   new_lb||new_ulb1  8192000 (contiguous 8192x1000)
//   [17580032)  logits_x_ulb_2 6144000
// ============================================================================
extern "C" void kernel_launch(void* const* d_in, const int* in_sizes, int n_in,
                              void* d_out, int out_size) {
    const float* anchor   = (const float*)d_in[0];
    const float* positive = (const float*)d_in[1];
    const float* lb_feat  = (const float*)d_in[2];
    const float* lb_oh    = (const float*)d_in[3];
    const float* lg_ulb1  = (const float*)d_in[5];
    const float* lg_ulb2  = (const float*)d_in[6];
    float* out = (float*)d_out;

    cudaMemcpyAsync(out,            anchor,   (size_t)NU * D  * sizeof(float), cudaMemcpyDeviceToDevice, 0);
    cudaMemcpyAsync(out + 3145728,  positive, (size_t)NU * D  * sizeof(float), cudaMemcpyDeviceToDevice, 0);
    cudaMemcpyAsync(out + 6291456,  lb_feat,  (size_t)NL * D  * sizeof(float), cudaMemcpyDeviceToDevice, 0);
    cudaMemcpyAsync(out + 7340032,  lb_oh,    (size_t)NL * CC * sizeof(float), cudaMemcpyDeviceToDevice, 0);
    cudaMemcpyAsync(out + 17580032, lg_ulb2,  (size_t)NU * CC * sizeof(float), cudaMemcpyDeviceToDevice, 0);

    void* rsum_ptr = nullptr;
    cudaGetSymbolAddress(&rsum_ptr, g_rsum);
    cudaMemsetAsync(rsum_ptr, 0, NT * sizeof(float), 0);

    normalize_kernel<<<NT, 128>>>(lb_feat, anchor);
    classval_kernel<<<NT, 256>>>(lb_oh, lg_ulb1);
    transpose_cv_kernel<<<dim3((NT - NL) / 32, 1024 / 32), 256>>>();

    cudaFuncSetAttribute(gemm1_kernel, cudaFuncAttributeMaxDynamicSharedMemorySize, 98304);
    cudaFuncSetAttribute(gemm2_kernel, cudaFuncAttributeMaxDynamicSharedMemorySize, 98304);

    gemm1_kernel<<<NB * (NB + 1) / 2, 256, 98304>>>();   // 2080 triangular blocks
    gemm2_kernel<<<dim3(8, 64), 256, 98304>>>(out + 9388032);
    scatter_kernel<<<NT, 256>>>(out + 9388032);
}

// round 7
// speedup vs baseline: 11.7261x; 1.3383x over previous
#include <cuda_runtime.h>
#include <cuda_fp16.h>
#include <cstdint>

// Problem sizes
static constexpr int NL = 2048;
static constexpr int NU = 6144;
static constexpr int NT = 8192;   // NL + NU
static constexpr int D  = 512;
static constexpr int CC = 1000;

// Scratch (device globals; no allocation allowed)
__device__ __half g_nh[(size_t)NT * D];      // normalized feats fp16 (8MB)
__device__ float  g_cv[(size_t)NT * CC];     // class_val fp32 (rows >= NL used)
__device__ __half g_cvT[(size_t)1024 * NT];  // class_val^T fp16 (cols >= NL used)
__device__ __half g_E[(size_t)NT * NT];      // exp(S) fp16 (134MB)
__device__ float  g_rsum[NT];                // softmax denominators (atomic-accumulated)
__device__ int    g_label[NL];               // argmax of lb_one_hot rows

// ============================================================================
// Helpers
// ============================================================================
__device__ __forceinline__ uint32_t smem_u32(const void* p) {
    uint32_t a;
    asm("{ .reg .u64 t; cvta.to.shared.u64 t, %1; cvt.u32.u64 %0, t; }" : "=r"(a) : "l"(p));
    return a;
}
// swizzled byte offset inside a tile of 128B rows (8 x 16B segments per row)
__device__ __forceinline__ uint32_t smoff(int row, int seg) {
    return (uint32_t)(row * 128 + ((seg ^ (row & 7)) << 4));
}
#define CP16(dst, src) \
    asm volatile("cp.async.cg.shared.global [%0], [%1], 16;" :: "r"(dst), "l"(src) : "memory")
#define CP_COMMIT() asm volatile("cp.async.commit_group;" ::: "memory")
#define CP_WAIT2() asm volatile("cp.async.wait_group 2;" ::: "memory")

__device__ __forceinline__ void ldm_x4(uint32_t* r, uint32_t addr) {
    asm volatile("ldmatrix.sync.aligned.m8n8.x4.shared.b16 {%0,%1,%2,%3}, [%4];"
                 : "=r"(r[0]), "=r"(r[1]), "=r"(r[2]), "=r"(r[3]) : "r"(addr));
}
__device__ __forceinline__ void mma16816(float* d, const uint32_t* a, const uint32_t* b) {
    asm volatile(
        "mma.sync.aligned.m16n8k16.row.col.f32.f16.f16.f32 "
        "{%0,%1,%2,%3}, {%4,%5,%6,%7}, {%8,%9}, {%0,%1,%2,%3};"
        : "+f"(d[0]), "+f"(d[1]), "+f"(d[2]), "+f"(d[3])
        : "r"(a[0]), "r"(a[1]), "r"(a[2]), "r"(a[3]), "r"(b[0]), "r"(b[1]));
}

// FMA-only exp, valid for |x| <= ~11, rel err < 2e-7
__device__ __forceinline__ float fast_expf(float x) {
    float z = x * 1.4426950408889634f;
    float n = rintf(z);
    float r = fmaf(n, -0.6931471824645996f, x);
    r = fmaf(n, 1.9046542743e-9f, r);
    float p = 1.3888889225e-3f;
    p = fmaf(p, r, 8.3333337680e-3f);
    p = fmaf(p, r, 4.1666667908e-2f);
    p = fmaf(p, r, 1.6666667163e-1f);
    p = fmaf(p, r, 5.0e-1f);
    p = fmaf(p, r, 1.0f);
    p = fmaf(p, r, 1.0f);
    float s = __int_as_float(((int)n + 127) << 23);
    return p * s;
}

__device__ __forceinline__ float blockMax256(float v) {
    __shared__ float s[8];
    #pragma unroll
    for (int o = 16; o > 0; o >>= 1) v = fmaxf(v, __shfl_xor_sync(0xffffffffu, v, o));
    if ((threadIdx.x & 31) == 0) s[threadIdx.x >> 5] = v;
    __syncthreads();
    float r = s[0];
    #pragma unroll
    for (int i = 1; i < 8; i++) r = fmaxf(r, s[i]);
    __syncthreads();
    return r;
}
__device__ __forceinline__ float blockSum256(float v) {
    __shared__ float s[8];
    #pragma unroll
    for (int o = 16; o > 0; o >>= 1) v += __shfl_xor_sync(0xffffffffu, v, o);
    if ((threadIdx.x & 31) == 0) s[threadIdx.x >> 5] = v;
    __syncthreads();
    float r = s[0];
    #pragma unroll
    for (int i = 1; i < 8; i++) r += s[i];
    __syncthreads();
    return r;
}

// ============================================================================
// Kernel 1: L2-normalize concat(lb_feat, anchor) -> fp16
// ============================================================================
__global__ void normalize_kernel(const float* __restrict__ lb_feat,
                                 const float* __restrict__ anchor) {
    const int row = blockIdx.x;
    const int t = threadIdx.x;
    const float* src = (row < NL) ? lb_feat + (size_t)row * D
                                  : anchor + (size_t)(row - NL) * D;
    float4 v = ((const float4*)src)[t];
    float ss = v.x * v.x + v.y * v.y + v.z * v.z + v.w * v.w;
    #pragma unroll
    for (int o = 16; o > 0; o >>= 1) ss += __shfl_xor_sync(0xffffffffu, ss, o);
    __shared__ float ws[4];
    if ((t & 31) == 0) ws[t >> 5] = ss;
    __syncthreads();
    float tot = ws[0] + ws[1] + ws[2] + ws[3];
    float sc = 1.0f / fmaxf(sqrtf(tot), 1e-12f);
    __half2 hA = __floats2half2_rn(v.x * sc, v.y * sc);
    __half2 hB = __floats2half2_rn(v.z * sc, v.w * sc);
    uint2 hp;
    hp.x = *(uint32_t*)&hA; hp.y = *(uint32_t*)&hB;
    ((uint2*)(g_nh + (size_t)row * D))[t] = hp;
}

// ============================================================================
// Kernel 2: rows < NL: extract label (argmax of one-hot).
//           rows >= NL: softmax(logits_x_ulb_1) -> g_cv.
// ============================================================================
__global__ void classval_kernel(const float* __restrict__ lb_one_hot,
                                const float* __restrict__ logits) {
    const int row = blockIdx.x;
    const int t = threadIdx.x;
    if (row < NL) {
        const float* src = lb_one_hot + (size_t)row * CC;
        #pragma unroll
        for (int q = 0; q < 4; q++) {
            int c = t + q * 256;
            if (c < CC && src[c] > 0.5f) g_label[row] = c;
        }
        return;
    }
    const float* src = logits + (size_t)(row - NL) * CC;
    float* dst = g_cv + (size_t)row * CC;
    float v[4];
    float mx = -1e30f;
    #pragma unroll
    for (int q = 0; q < 4; q++) {
        int j = t + q * 256;
        v[q] = (j < CC) ? src[j] : -1e30f;
        mx = fmaxf(mx, v[q]);
    }
    mx = blockMax256(mx);
    float sum = 0.f;
    #pragma unroll
    for (int q = 0; q < 4; q++) {
        int j = t + q * 256;
        float e = (j < CC) ? fast_expf(v[q] - mx) : 0.f;
        v[q] = e;
        sum += e;
    }
    sum = blockSum256(sum);
    float inv = 1.0f / sum;
    #pragma unroll
    for (int q = 0; q < 4; q++) {
        int j = t + q * 256;
        if (j < CC) dst[j] = v[q] * inv;
    }
}

// ============================================================================
// Kernel 3: transpose g_cv rows [NL,NT) fp32 -> g_cvT[c][k] fp16 (k >= NL)
// ============================================================================
__global__ void transpose_cv_kernel() {
    __shared__ float s[32][33];
    const int k0 = NL + blockIdx.x * 32, c0 = blockIdx.y * 32;
    const int tx = threadIdx.x & 31, ty = threadIdx.x >> 5;
    #pragma unroll
    for (int q = 0; q < 4; q++) {
        int k = k0 + ty + q * 8, c = c0 + tx;
        s[ty + q * 8][tx] = (c < CC) ? g_cv[(size_t)k * CC + c] : 0.f;
    }
    __syncthreads();
    #pragma unroll
    for (int q = 0; q < 4; q++) {
        int c = c0 + ty + q * 8, k = k0 + tx;
        g_cvT[(size_t)c * NT + k] = __float2half_rn(s[tx][ty + q * 8]);
    }
}

// ============================================================================
// Kernel 4: GEMM1 (HMMA): dot = n@n^T (single-pass fp16); E = exp(10*dot)
// SYMMETRIC: only upper-triangular 128x128 blocks (bi <= bj); off-diagonal
// blocks also write the transposed tile (staged through SMEM).
// Fused rowsums -> g_rsum via warp-reduced atomics.
// kc=64, 3-stage cp.async; stage = A 16KB | B 16KB = 32KB; 3 = 96KB; 2 CTA/SM.
// ============================================================================
__device__ __forceinline__ void g1_load(uint32_t sb, int s, int c, int i0, int j0, int t) {
    #pragma unroll
    for (int q = 0; q < 4; q++) {
        int u = t + q * 256, row = u >> 3, seg = u & 7;
        uint32_t so = smoff(row, seg);
        uint32_t dA = sb + s * 32768 + so;
        size_t ga = ((size_t)(i0 + row) * D + c * 64 + seg * 8) * 2;
        size_t gb = ((size_t)(j0 + row) * D + c * 64 + seg * 8) * 2;
        CP16(dA,         (const char*)g_nh + ga);
        CP16(dA + 16384, (const char*)g_nh + gb);
    }
}

static constexpr int NB = NT / 128;  // 64 blocks per dim
static constexpr int TP = 136;       // transpose-stage pitch in halves

__global__ __launch_bounds__(256, 2) void gemm1_kernel() {
    extern __shared__ char smem[];
    const uint32_t sb = smem_u32(smem);
    const int t = threadIdx.x, lane = t & 31, w = t >> 5;
    const int wm = w >> 2, wn = w & 3;

    // triangular decode: blockIdx.x -> (bi, bj), bi <= bj
    int bi = 0, rem = blockIdx.x;
    while (rem >= NB - bi) { rem -= NB - bi; bi++; }
    const int bj = bi + rem;
    const int i0 = bi * 128, j0 = bj * 128;

    float acc[4][4][4];
    #pragma unroll
    for (int a = 0; a < 4; a++)
        #pragma unroll
        for (int b = 0; b < 4; b++)
            #pragma unroll
            for (int cth = 0; cth < 4; cth++) acc[a][b][cth] = 0.f;

    const int rA = wm * 64 + (lane & 15);
    const int sA = lane >> 4;
    const int rB = wn * 32 + ((lane >> 4) & 1) * 8 + (lane & 7);
    const int sB = (lane >> 3) & 1;

    g1_load(sb, 0, 0, i0, j0, t); CP_COMMIT();
    g1_load(sb, 1, 1, i0, j0, t); CP_COMMIT();

    constexpr int NCH = D / 64;  // 8 chunks
    for (int c = 0; c < NCH; c++) {
        const int st = c % 3;
        if (c + 2 < NCH) g1_load(sb, (c + 2) % 3, c + 2, i0, j0, t);
        CP_COMMIT();   // always commit -> WAIT2 retires chunk c
        CP_WAIT2();
        __syncthreads();
        const uint32_t bA = sb + st * 32768;
        const uint32_t bB = bA + 16384;
        #pragma unroll
        for (int kk = 0; kk < 4; kk++) {
            uint32_t af[4][4], bf[8];
            #pragma unroll
            for (int mt = 0; mt < 4; mt++)
                ldm_x4(af[mt], bA + smoff(rA + mt * 16, 2 * kk + sA));
            #pragma unroll
            for (int jj = 0; jj < 2; jj++)
                ldm_x4(bf + jj * 4, bB + smoff(rB + jj * 16, 2 * kk + sB));
            #pragma unroll
            for (int mt = 0; mt < 4; mt++)
                #pragma unroll
                for (int nt = 0; nt < 4; nt++)
                    mma16816(acc[mt][nt], af[mt], bf + nt * 2);
        }
        __syncthreads();
    }
    // All stage-buffer reads done; smem reusable for transpose staging.

    // Epilogue: E = exp(10*acc) -> fp16; fused row sums.
    const int g = lane >> 2, cq = lane & 3;
    __half* sT = (__half*)smem;  // pitch TP halves
    #pragma unroll
    for (int mt = 0; mt < 4; mt++) {
        #pragma unroll
        for (int h = 0; h < 2; h++) {
            const int rl = wm * 64 + mt * 16 + g + h * 8;      // local row
            __half* erow = g_E + (size_t)(i0 + rl) * NT + j0 + wn * 32;
            float rs = 0.f;
            #pragma unroll
            for (int nt = 0; nt < 4; nt++) {
                float e0 = fast_expf(acc[mt][nt][2 * h] * 10.f);
                float e1 = fast_expf(acc[mt][nt][2 * h + 1] * 10.f);
                __half2 p = __floats2half2_rn(e0, e1);
                *(__half2*)(erow + nt * 8 + cq * 2) = p;
                float2 pf = __half22float2(p);   // sum the rounded values
                rs += pf.x + pf.y;
                if (bi != bj) {
                    const int cl = wn * 32 + nt * 8 + cq * 2;
                    sT[(size_t)cl * TP + rl]       = __low2half(p);
                    sT[(size_t)(cl + 1) * TP + rl] = __high2half(p);
                }
            }
            // reduce across the 4 cq lanes sharing this row
            rs += __shfl_xor_sync(0xffffffffu, rs, 1);
            rs += __shfl_xor_sync(0xffffffffu, rs, 2);
            if (cq == 0) atomicAdd(&g_rsum[i0 + rl], rs);
        }
    }
    if (bi != bj) {
        __syncthreads();
        // coalesced write of transposed tile + its row sums (= column sums)
        #pragma unroll
        for (int q = 0; q < 8; q++) {
            int u = t + q * 256;
            int row = u >> 4, seg = u & 15;  // seg == lane & 15
            uint4 v = *(const uint4*)(sT + row * TP + seg * 8);
            *(uint4*)(g_E + (size_t)(j0 + row) * NT + i0 + seg * 8) = v;
            const __half2* hh = (const __half2*)&v;
            float s = 0.f;
            #pragma unroll
            for (int k = 0; k < 4; k++) {
                float2 f = __half22float2(hh[k]);
                s += f.x + f.y;
            }
            s += __shfl_xor_sync(0xffffffffu, s, 1);
            s += __shfl_xor_sync(0xffffffffu, s, 2);
            s += __shfl_xor_sync(0xffffffffu, s, 4);
            s += __shfl_xor_sync(0xffffffffu, s, 8);
            if (seg == 0) atomicAdd(&g_rsum[j0 + row], s);
        }
    }
}

// ============================================================================
// Kernel 5: GEMM2 (HMMA): out = (E[:,2048:] @ cvT[:,2048:]^T) / rsum
// K = 6144 (96 chunks of 64). 3-stage pipeline, stage 32KB (A|B), 2 CTAs/SM.
// ============================================================================
__device__ __forceinline__ void g2_load(uint32_t sb, int s, int c, int i0, int j0, int t) {
    #pragma unroll
    for (int q = 0; q < 4; q++) {
        int u = t + q * 256, row = u >> 3, seg = u & 7;
        uint32_t so = smoff(row, seg);
        uint32_t dA = sb + s * 32768 + so;
        size_t ga = ((size_t)(i0 + row) * NT + NL + c * 64 + seg * 8) * 2;
        size_t gb = ((size_t)(j0 + row) * NT + NL + c * 64 + seg * 8) * 2;
        CP16(dA,         (const char*)g_E + ga);
        CP16(dA + 16384, (const char*)g_cvT + gb);
    }
}

__global__ __launch_bounds__(256, 2) void gemm2_kernel(float* __restrict__ out) {
    extern __shared__ char smem[];
    const uint32_t sb = smem_u32(smem);
    const int t = threadIdx.x, lane = t & 31, w = t >> 5;
    const int wm = w >> 2, wn = w & 3;
    const int i0 = blockIdx.y * 128, j0 = blockIdx.x * 128;

    float acc[4][4][4];
    #pragma unroll
    for (int a = 0; a < 4; a++)
        #pragma unroll
        for (int b = 0; b < 4; b++)
            #pragma unroll
            for (int cth = 0; cth < 4; cth++) acc[a][b][cth] = 0.f;

    const int rA = wm * 64 + (lane & 15);
    const int sA = lane >> 4;
    const int rB = wn * 32 + ((lane >> 4) & 1) * 8 + (lane & 7);
    const int sB = (lane >> 3) & 1;

    g2_load(sb, 0, 0, i0, j0, t); CP_COMMIT();
    g2_load(sb, 1, 1, i0, j0, t); CP_COMMIT();

    constexpr int NCH = (NT - NL) / 64;  // 96
    for (int c = 0; c < NCH; c++) {
        const int st = c % 3;
        if (c + 2 < NCH) g2_load(sb, (c + 2) % 3, c + 2, i0, j0, t);
        CP_COMMIT();
        CP_WAIT2();
        __syncthreads();
        const uint32_t bA = sb + st * 32768;
        const uint32_t bB = bA + 16384;
        #pragma unroll
        for (int kk = 0; kk < 4; kk++) {
            uint32_t af[4][4], bf[8];
            #pragma unroll
            for (int mt = 0; mt < 4; mt++)
                ldm_x4(af[mt], bA + smoff(rA + mt * 16, 2 * kk + sA));
            #pragma unroll
            for (int jj = 0; jj < 2; jj++)
                ldm_x4(bf + jj * 4, bB + smoff(rB + jj * 16, 2 * kk + sB));
            #pragma unroll
            for (int mt = 0; mt < 4; mt++)
                #pragma unroll
                for (int nt = 0; nt < 4; nt++)
                    mma16816(acc[mt][nt], af[mt], bf + nt * 2);
        }
        __syncthreads();
    }

    const int g = lane >> 2, cq = lane & 3;
    #pragma unroll
    for (int mt = 0; mt < 4; mt++) {
        #pragma unroll
        for (int h = 0; h < 2; h++) {
            const int row = i0 + wm * 64 + mt * 16 + g + h * 8;
            const float inv = 1.0f / g_rsum[row];
            float* crow = out + (size_t)row * CC;
            #pragma unroll
            for (int nt = 0; nt < 4; nt++) {
                int col = j0 + wn * 32 + nt * 8 + cq * 2;
                if (col < CC) {
                    float2 v = make_float2(acc[mt][nt][2 * h] * inv,
                                           acc[mt][nt][2 * h + 1] * inv);
                    *(float2*)(crow + col) = v;
                }
            }
        }
    }
}

// ============================================================================
// Kernel 6: scatter the labeled (one-hot) K-range into out.
// out[i][c] += (sum_{j<NL, label[j]==c} E[i][j]) / rsum[i]
// ============================================================================
__global__ __launch_bounds__(256) void scatter_kernel(float* __restrict__ out) {
    __shared__ float accum[CC];
    __shared__ int lab[NL];
    const int i = blockIdx.x, t = threadIdx.x;
    #pragma unroll
    for (int q = 0; q < 4; q++) {
        int c = t + q * 256;
        if (c < CC) accum[c] = 0.f;
    }
    #pragma unroll
    for (int q = 0; q < 8; q++) lab[t + q * 256] = g_label[t + q * 256];
    __syncthreads();
    uint4 u = ((const uint4*)(g_E + (size_t)i * NT))[t];
    const __half2* h = (const __half2*)&u;
    const int j0 = t * 8;
    #pragma unroll
    for (int k = 0; k < 4; k++) {
        float2 f = __half22float2(h[k]);
        atomicAdd(&accum[lab[j0 + 2 * k]],     f.x);
        atomicAdd(&accum[lab[j0 + 2 * k + 1]], f.y);
    }
    __syncthreads();
    const float inv = 1.0f / g_rsum[i];
    float* crow = out + (size_t)i * CC;
    #pragma unroll
    for (int q = 0; q < 4; q++) {
        int c = t + q * 256;
        if (c < CC) crow[c] += accum[c] * inv;
    }
}

// ============================================================================
// Launch. Output layout (float32):
//   [0)         anchor_feat    3145728
//   [3145728)   positive_feat  3145728
//   [6291456)   lb_feat        1048576
//   [7340032)   lb_one_hot     2048000
//   [9388032)   new_lb||new_ulb1  8192000 (contiguous 8192x1000)
//   [17580032)  logits_x_ulb_2 6144000
// ============================================================================
extern "C" void kernel_launch(void* const* d_in, const int* in_sizes, int n_in,
                              void* d_out, int out_size) {
    const float* anchor   = (const float*)d_in[0];
    const float* positive = (const float*)d_in[1];
    const float* lb_feat  = (const float*)d_in[2];
    const float* lb_oh    = (const float*)d_in[3];
    const float* lg_ulb1  = (const float*)d_in[5];
    const float* lg_ulb2  = (const float*)d_in[6];
    float* out = (float*)d_out;

    cudaMemcpyAsync(out,            anchor,   (size_t)NU * D  * sizeof(float), cudaMemcpyDeviceToDevice, 0);
    cudaMemcpyAsync(out + 3145728,  positive, (size_t)NU * D  * sizeof(float), cudaMemcpyDeviceToDevice, 0);
    cudaMemcpyAsync(out + 6291456,  lb_feat,  (size_t)NL * D  * sizeof(float), cudaMemcpyDeviceToDevice, 0);
    cudaMemcpyAsync(out + 7340032,  lb_oh,    (size_t)NL * CC * sizeof(float), cudaMemcpyDeviceToDevice, 0);
    cudaMemcpyAsync(out + 17580032, lg_ulb2,  (size_t)NU * CC * sizeof(float), cudaMemcpyDeviceToDevice, 0);

    void* rsum_ptr = nullptr;
    cudaGetSymbolAddress(&rsum_ptr, g_rsum);
    cudaMemsetAsync(rsum_ptr, 0, NT * sizeof(float), 0);

    normalize_kernel<<<NT, 128>>>(lb_feat, anchor);
    classval_kernel<<<NT, 256>>>(lb_oh, lg_ulb1);
    transpose_cv_kernel<<<dim3((NT - NL) / 32, 1024 / 32), 256>>>();

    cudaFuncSetAttribute(gemm1_kernel, cudaFuncAttributeMaxDynamicSharedMemorySize, 98304);
    cudaFuncSetAttribute(gemm2_kernel, cudaFuncAttributeMaxDynamicSharedMemorySize, 98304);

    gemm1_kernel<<<NB * (NB + 1) / 2, 256, 98304>>>();   // 2080 triangular blocks
    gemm2_kernel<<<dim3(8, 64), 256, 98304>>>(out + 9388032);
    scatter_kernel<<<NT, 256>>>(out + 9388032);
}